// round 9
// baseline (speedup 1.0000x reference)
#include <cuda_runtime.h>
#include <cuda_bf16.h>
#include <stdint.h>

#define D_MODEL 1024
#define HEADS   16
#define DK      64
#define BATCH   2
#define SEQ     2048
#define M_TOK   (BATCH * SEQ)
#define BH      (BATCH * HEADS)

// ---------------- scratch (static device globals; no runtime alloc) ----------
// pre-split weights [N][K]
__device__ uint16_t g_wq_hi[D_MODEL * D_MODEL], g_wq_lo[D_MODEL * D_MODEL];
__device__ uint16_t g_wk_hi[D_MODEL * D_MODEL], g_wk_lo[D_MODEL * D_MODEL];
__device__ uint16_t g_wv_hi[D_MODEL * D_MODEL], g_wv_lo[D_MODEL * D_MODEL];
__device__ uint16_t g_wo_hi[D_MODEL * D_MODEL], g_wo_lo[D_MODEL * D_MODEL];
// pre-split inputs [M][K]
__device__ uint16_t g_aq_hi[M_TOK * D_MODEL], g_aq_lo[M_TOK * D_MODEL];
__device__ uint16_t g_ak_hi[M_TOK * D_MODEL], g_ak_lo[M_TOK * D_MODEL];
__device__ uint16_t g_av_hi[M_TOK * D_MODEL], g_av_lo[M_TOK * D_MODEL];
// projected split tensors: Q,K [bh][s][d] (Q pre-scaled), V^T [bh][d][s]
__device__ uint16_t g_q_hi[BH * SEQ * DK], g_q_lo[BH * SEQ * DK];
__device__ uint16_t g_k_hi[BH * SEQ * DK], g_k_lo[BH * SEQ * DK];
__device__ uint16_t g_vt_hi[BH * DK * SEQ], g_vt_lo[BH * DK * SEQ];
// attention output, split [B,S,D_MODEL]
__device__ uint16_t g_ctx_hi[M_TOK * D_MODEL], g_ctx_lo[M_TOK * D_MODEL];

// ---------------- helpers ----------------------------------------------------
__device__ __forceinline__ uint16_t f2bf_bits(float x) {
    __nv_bfloat16 h = __float2bfloat16(x);
    return *reinterpret_cast<uint16_t*>(&h);
}
__device__ __forceinline__ float bfbits2f(uint16_t b) {
    __nv_bfloat16 h = *reinterpret_cast<__nv_bfloat16*>(&b);
    return __bfloat162float(h);
}
__device__ __forceinline__ void split_bf16(float x, uint16_t& hi, uint16_t& lo) {
    hi = f2bf_bits(x);
    lo = f2bf_bits(x - bfbits2f(hi));
}
__device__ __forceinline__ void split_pack2(float p0, float p1,
                                            uint32_t& hi, uint32_t& lo) {
    uint16_t h0, l0, h1, l1;
    split_bf16(p0, h0, l0);
    split_bf16(p1, h1, l1);
    hi = (uint32_t)h0 | ((uint32_t)h1 << 16);
    lo = (uint32_t)l0 | ((uint32_t)l1 << 16);
}

__device__ __forceinline__ void mma16816(float* c, const uint32_t* a, const uint32_t* b) {
    asm volatile(
        "mma.sync.aligned.m16n8k16.row.col.f32.bf16.bf16.f32 "
        "{%0,%1,%2,%3}, {%4,%5,%6,%7}, {%8,%9}, {%0,%1,%2,%3};"
        : "+f"(c[0]), "+f"(c[1]), "+f"(c[2]), "+f"(c[3])
        : "r"(a[0]), "r"(a[1]), "r"(a[2]), "r"(a[3]), "r"(b[0]), "r"(b[1]));
}

// ---------------- fp32 -> split bf16 elementwise ----------------------------
__global__ __launch_bounds__(256) void split_f32_k(
    const float* __restrict__ src, uint16_t* __restrict__ hi,
    uint16_t* __restrict__ lo)
{
    int i = (blockIdx.x * 256 + threadIdx.x) * 4;
    float4 v = *(const float4*)&src[i];
    ushort4 H, L;
    split_bf16(v.x, H.x, L.x);
    split_bf16(v.y, H.y, L.y);
    split_bf16(v.z, H.z, L.z);
    split_bf16(v.w, H.w, L.w);
    *(ushort4*)&hi[i] = H;
    *(ushort4*)&lo[i] = L;
}

// ---------------- split-bf16 tensor GEMM v2 (pre-split operands) ------------
// C = A[M,K] * W[N,K]^T + bias;  C ~= Ah*Wh + Ah*Wl + Al*Wh.
// mode 0: -> g_q (split, scaled 0.125, [bh][s][d])
// mode 1: -> g_k (split, [bh][s][d])
// mode 2: -> g_vt (split, [bh][d][s]  TRANSPOSED)
// mode 3: -> Cflat fp32 [M][N]
#define BM  128
#define BN  128
#define BK  32
#define BKP 40

__global__ __launch_bounds__(256, 2) void mma_gemm2_k(
    const uint16_t* __restrict__ Ah, const uint16_t* __restrict__ Al,
    const uint16_t* __restrict__ Wh, const uint16_t* __restrict__ Wl,
    const float* __restrict__ bias, float* __restrict__ Cflat, int mode)
{
    __shared__ uint16_t Ahi[BM][BKP], Alo[BM][BKP];
    __shared__ uint16_t Whi[BN][BKP], Wlo[BN][BKP];

    const int tid  = threadIdx.x;
    const int lane = tid & 31, w = tid >> 5;
    const int wm = w & 1, wn = w >> 1;
    const int g  = lane >> 2, tq = lane & 3;
    const int m0 = blockIdx.y * BM, n0 = blockIdx.x * BN;

    float acc[4][4][4];
#pragma unroll
    for (int mi = 0; mi < 4; mi++)
#pragma unroll
        for (int ni = 0; ni < 4; ni++)
#pragma unroll
            for (int r = 0; r < 4; r++) acc[mi][ni][r] = 0.f;

    for (int kt = 0; kt < D_MODEL; kt += BK) {
        __syncthreads();
#pragma unroll
        for (int l = 0; l < 2; l++) {
            int id  = tid + l * 256;
            int row = id >> 2;
            int c   = (id & 3) << 3;
            size_t asrc = (size_t)(m0 + row) * D_MODEL + kt + c;
            size_t wsrc = (size_t)(n0 + row) * D_MODEL + kt + c;
            *(uint4*)&Ahi[row][c] = *(const uint4*)&Ah[asrc];
            *(uint4*)&Alo[row][c] = *(const uint4*)&Al[asrc];
            *(uint4*)&Whi[row][c] = *(const uint4*)&Wh[wsrc];
            *(uint4*)&Wlo[row][c] = *(const uint4*)&Wl[wsrc];
        }
        __syncthreads();

#pragma unroll
        for (int s = 0; s < 2; s++) {
            const int kb = s * 16 + tq * 2;
            uint32_t bhf[4][2], blf[4][2];
#pragma unroll
            for (int ni = 0; ni < 4; ni++) {
                int n = wn * 32 + ni * 8 + g;
                bhf[ni][0] = *(const uint32_t*)&Whi[n][kb];
                bhf[ni][1] = *(const uint32_t*)&Whi[n][kb + 8];
                blf[ni][0] = *(const uint32_t*)&Wlo[n][kb];
                blf[ni][1] = *(const uint32_t*)&Wlo[n][kb + 8];
            }
#pragma unroll
            for (int mi = 0; mi < 4; mi++) {
                int r0 = wm * 64 + mi * 16 + g;
                uint32_t ah[4], al[4];
                ah[0] = *(const uint32_t*)&Ahi[r0    ][kb];
                ah[1] = *(const uint32_t*)&Ahi[r0 + 8][kb];
                ah[2] = *(const uint32_t*)&Ahi[r0    ][kb + 8];
                ah[3] = *(const uint32_t*)&Ahi[r0 + 8][kb + 8];
                al[0] = *(const uint32_t*)&Alo[r0    ][kb];
                al[1] = *(const uint32_t*)&Alo[r0 + 8][kb];
                al[2] = *(const uint32_t*)&Alo[r0    ][kb + 8];
                al[3] = *(const uint32_t*)&Alo[r0 + 8][kb + 8];
#pragma unroll
                for (int ni = 0; ni < 4; ni++) {
                    mma16816(acc[mi][ni], ah, bhf[ni]);
                    mma16816(acc[mi][ni], ah, blf[ni]);
                    mma16816(acc[mi][ni], al, bhf[ni]);
                }
            }
        }
    }

    const float sc = (mode == 0) ? 0.125f : 1.0f;

#pragma unroll
    for (int mi = 0; mi < 4; mi++) {
#pragma unroll
        for (int ni = 0; ni < 4; ni++) {
#pragma unroll
            for (int half = 0; half < 2; half++) {
                int m = m0 + wm * 64 + mi * 16 + g + half * 8;
#pragma unroll
                for (int cc = 0; cc < 2; cc++) {
                    int n = n0 + wn * 32 + ni * 8 + tq * 2 + cc;
                    float v = acc[mi][ni][half * 2 + cc] + bias[n];
                    if (mode == 3) {
                        Cflat[(size_t)m * D_MODEL + n] = v;
                    } else {
                        int b_ = m >> 11, ss = m & (SEQ - 1);
                        int h  = n >> 6,  d  = n & 63;
                        int bh = b_ * HEADS + h;
                        uint16_t vh, vl;
                        split_bf16(v * sc, vh, vl);
                        if (mode == 0) {
                            size_t idx = ((size_t)bh * SEQ + ss) * DK + d;
                            g_q_hi[idx] = vh; g_q_lo[idx] = vl;
                        } else if (mode == 1) {
                            size_t idx = ((size_t)bh * SEQ + ss) * DK + d;
                            g_k_hi[idx] = vh; g_k_lo[idx] = vl;
                        } else {
                            size_t idx = ((size_t)bh * DK + d) * SEQ + ss;
                            g_vt_hi[idx] = vh; g_vt_lo[idx] = vl;
                        }
                    }
                }
            }
        }
    }
}

// ---------------- tensor-core flash attention (split bf16) ------------------
// 256 threads = 8 warps; warp w owns q rows [w*16, w*16+16) of a 128-row block.
// 64-key tiles. Q smem is transient, aliased over the K/V buffers.
#define FSTR 72

__global__ __launch_bounds__(256) void flash_mma_k()
{
    extern __shared__ uint16_t smu[];
    uint16_t* Khi = smu;                    // [64][FSTR]
    uint16_t* Klo = smu + 64 * FSTR;
    uint16_t* Vhi = smu + 2 * 64 * FSTR;    // V^T tile [d][key]
    uint16_t* Vlo = smu + 3 * 64 * FSTR;
    uint16_t* Qhi = smu;                    // alias: [128][FSTR]
    uint16_t* Qlo = smu + 128 * FSTR;

    const int tid  = threadIdx.x;
    const int lane = tid & 31, w = tid >> 5;
    const int g = lane >> 2, tq = lane & 3;
    const int bh = blockIdx.y;
    const int b  = bh >> 4, h = bh & 15;
    const int qbase = blockIdx.x * 128;
    const int q0 = w * 16;

    // stage Q block (128 rows)
#pragma unroll
    for (int l = 0; l < 4; l++) {
        int id  = tid + l * 256;
        int row = id >> 3;
        int dc  = (id & 7) << 3;
        size_t src = ((size_t)bh * SEQ + qbase + row) * DK + dc;
        *(uint4*)&Qhi[row * FSTR + dc] = *(const uint4*)&g_q_hi[src];
        *(uint4*)&Qlo[row * FSTR + dc] = *(const uint4*)&g_q_lo[src];
    }
    __syncthreads();

    // Q fragments to registers
    uint32_t aqh[4][4], aql[4][4];
#pragma unroll
    for (int t = 0; t < 4; t++) {
        int c0 = 16 * t + 2 * tq;
        aqh[t][0] = *(const uint32_t*)&Qhi[(q0 + g    ) * FSTR + c0];
        aqh[t][1] = *(const uint32_t*)&Qhi[(q0 + g + 8) * FSTR + c0];
        aqh[t][2] = *(const uint32_t*)&Qhi[(q0 + g    ) * FSTR + c0 + 8];
        aqh[t][3] = *(const uint32_t*)&Qhi[(q0 + g + 8) * FSTR + c0 + 8];
        aql[t][0] = *(const uint32_t*)&Qlo[(q0 + g    ) * FSTR + c0];
        aql[t][1] = *(const uint32_t*)&Qlo[(q0 + g + 8) * FSTR + c0];
        aql[t][2] = *(const uint32_t*)&Qlo[(q0 + g    ) * FSTR + c0 + 8];
        aql[t][3] = *(const uint32_t*)&Qlo[(q0 + g + 8) * FSTR + c0 + 8];
    }

    float m0 = -1e30f, m1 = -1e30f, l0 = 0.f, l1 = 0.f;
    float oacc[8][4];
#pragma unroll
    for (int dj = 0; dj < 8; dj++)
#pragma unroll
        for (int r = 0; r < 4; r++) oacc[dj][r] = 0.f;

    for (int kt = 0; kt < SEQ; kt += 64) {
        __syncthreads();   // frag extraction / prev-tile reads done
        // stage K and V^T tiles
#pragma unroll
        for (int l = 0; l < 2; l++) {
            int id  = tid + l * 256;
            int row = id >> 3;
            int dc  = (id & 7) << 3;
            size_t ksrc = ((size_t)bh * SEQ + kt + row) * DK + dc;
            *(uint4*)&Khi[row * FSTR + dc] = *(const uint4*)&g_k_hi[ksrc];
            *(uint4*)&Klo[row * FSTR + dc] = *(const uint4*)&g_k_lo[ksrc];
            size_t vsrc = ((size_t)bh * DK + row) * SEQ + kt + dc;
            *(uint4*)&Vhi[row * FSTR + dc] = *(const uint4*)&g_vt_hi[vsrc];
            *(uint4*)&Vlo[row * FSTR + dc] = *(const uint4*)&g_vt_lo[vsrc];
        }
        __syncthreads();

        // ---- S = Q.K^T (3-pass split) ----
        float sacc[8][4];
#pragma unroll
        for (int j = 0; j < 8; j++)
#pragma unroll
            for (int r = 0; r < 4; r++) sacc[j][r] = 0.f;

#pragma unroll
        for (int j = 0; j < 8; j++) {
            int krow = (8 * j + g) * FSTR;
#pragma unroll
            for (int t = 0; t < 4; t++) {
                int c0 = 16 * t + 2 * tq;
                uint32_t bhf[2], blf[2];
                bhf[0] = *(const uint32_t*)&Khi[krow + c0];
                bhf[1] = *(const uint32_t*)&Khi[krow + c0 + 8];
                blf[0] = *(const uint32_t*)&Klo[krow + c0];
                blf[1] = *(const uint32_t*)&Klo[krow + c0 + 8];
                mma16816(sacc[j], aqh[t], bhf);
                mma16816(sacc[j], aqh[t], blf);
                mma16816(sacc[j], aql[t], bhf);
            }
        }

        // ---- online softmax ----
        float mx0 = -1e30f, mx1 = -1e30f;
#pragma unroll
        for (int j = 0; j < 8; j++) {
            mx0 = fmaxf(mx0, fmaxf(sacc[j][0], sacc[j][1]));
            mx1 = fmaxf(mx1, fmaxf(sacc[j][2], sacc[j][3]));
        }
#pragma unroll
        for (int off = 1; off <= 2; off <<= 1) {
            mx0 = fmaxf(mx0, __shfl_xor_sync(0xffffffffu, mx0, off));
            mx1 = fmaxf(mx1, __shfl_xor_sync(0xffffffffu, mx1, off));
        }
        float mn0 = fmaxf(m0, mx0), mn1 = fmaxf(m1, mx1);
        float al0 = __expf(m0 - mn0), al1 = __expf(m1 - mn1);
        m0 = mn0; m1 = mn1;

        float rs0 = 0.f, rs1 = 0.f;
#pragma unroll
        for (int j = 0; j < 8; j++) {
            sacc[j][0] = __expf(sacc[j][0] - mn0);
            sacc[j][1] = __expf(sacc[j][1] - mn0);
            sacc[j][2] = __expf(sacc[j][2] - mn1);
            sacc[j][3] = __expf(sacc[j][3] - mn1);
            rs0 += sacc[j][0] + sacc[j][1];
            rs1 += sacc[j][2] + sacc[j][3];
        }
#pragma unroll
        for (int off = 1; off <= 2; off <<= 1) {
            rs0 += __shfl_xor_sync(0xffffffffu, rs0, off);
            rs1 += __shfl_xor_sync(0xffffffffu, rs1, off);
        }
        l0 = l0 * al0 + rs0;
        l1 = l1 * al1 + rs1;
#pragma unroll
        for (int dj = 0; dj < 8; dj++) {
            oacc[dj][0] *= al0; oacc[dj][1] *= al0;
            oacc[dj][2] *= al1; oacc[dj][3] *= al1;
        }

        // ---- P -> split bf16 A-fragments ----
        uint32_t pah[4][4], pal[4][4];
#pragma unroll
        for (int t = 0; t < 4; t++) {
            split_pack2(sacc[2*t    ][0], sacc[2*t    ][1], pah[t][0], pal[t][0]);
            split_pack2(sacc[2*t    ][2], sacc[2*t    ][3], pah[t][1], pal[t][1]);
            split_pack2(sacc[2*t + 1][0], sacc[2*t + 1][1], pah[t][2], pal[t][2]);
            split_pack2(sacc[2*t + 1][2], sacc[2*t + 1][3], pah[t][3], pal[t][3]);
        }

        // ---- O += P.V (3-pass split) ----
#pragma unroll
        for (int dj = 0; dj < 8; dj++) {
            int vrow = (8 * dj + g) * FSTR;
#pragma unroll
            for (int t = 0; t < 4; t++) {
                int c0 = 16 * t + 2 * tq;
                uint32_t bhf[2], blf[2];
                bhf[0] = *(const uint32_t*)&Vhi[vrow + c0];
                bhf[1] = *(const uint32_t*)&Vhi[vrow + c0 + 8];
                blf[0] = *(const uint32_t*)&Vlo[vrow + c0];
                blf[1] = *(const uint32_t*)&Vlo[vrow + c0 + 8];
                mma16816(oacc[dj], pah[t], bhf);
                mma16816(oacc[dj], pah[t], blf);
                mma16816(oacc[dj], pal[t], bhf);
            }
        }
    }

    // epilogue: normalize, split, write ctx (split bf16, concat layout)
    float inv0 = 1.f / l0, inv1 = 1.f / l1;
    int s0 = qbase + q0 + g;
    int s1 = s0 + 8;
#pragma unroll
    for (int dj = 0; dj < 8; dj++) {
        int d = h * DK + 8 * dj + 2 * tq;
        uint32_t h0, lo0, h1, lo1;
        split_pack2(oacc[dj][0] * inv0, oacc[dj][1] * inv0, h0, lo0);
        split_pack2(oacc[dj][2] * inv1, oacc[dj][3] * inv1, h1, lo1);
        size_t i0 = (size_t)(b * SEQ + s0) * D_MODEL + d;
        size_t i1 = (size_t)(b * SEQ + s1) * D_MODEL + d;
        *(uint32_t*)&g_ctx_hi[i0] = h0;
        *(uint32_t*)&g_ctx_lo[i0] = lo0;
        *(uint32_t*)&g_ctx_hi[i1] = h1;
        *(uint32_t*)&g_ctx_lo[i1] = lo1;
    }
}

// ---------------- launch ----------------------------------------------------
extern "C" void kernel_launch(void* const* d_in, const int* in_sizes, int n_in,
                              void* d_out, int out_size)
{
    const float* q  = (const float*)d_in[0];
    const float* k  = (const float*)d_in[1];
    const float* v  = (const float*)d_in[2];
    const float* wq = (const float*)d_in[3];
    const float* bq = (const float*)d_in[4];
    const float* wk = (const float*)d_in[5];
    const float* bk = (const float*)d_in[6];
    const float* wv = (const float*)d_in[7];
    const float* bv = (const float*)d_in[8];
    const float* wo = (const float*)d_in[9];
    const float* bo = (const float*)d_in[10];
    float* out = (float*)d_out;

    uint16_t *p_wq_hi, *p_wq_lo, *p_wk_hi, *p_wk_lo, *p_wv_hi, *p_wv_lo;
    uint16_t *p_wo_hi, *p_wo_lo, *p_aq_hi, *p_aq_lo, *p_ak_hi, *p_ak_lo;
    uint16_t *p_av_hi, *p_av_lo, *p_ctx_hi, *p_ctx_lo;
    cudaGetSymbolAddress((void**)&p_wq_hi, g_wq_hi);
    cudaGetSymbolAddress((void**)&p_wq_lo, g_wq_lo);
    cudaGetSymbolAddress((void**)&p_wk_hi, g_wk_hi);
    cudaGetSymbolAddress((void**)&p_wk_lo, g_wk_lo);
    cudaGetSymbolAddress((void**)&p_wv_hi, g_wv_hi);
    cudaGetSymbolAddress((void**)&p_wv_lo, g_wv_lo);
    cudaGetSymbolAddress((void**)&p_wo_hi, g_wo_hi);
    cudaGetSymbolAddress((void**)&p_wo_lo, g_wo_lo);
    cudaGetSymbolAddress((void**)&p_aq_hi, g_aq_hi);
    cudaGetSymbolAddress((void**)&p_aq_lo, g_aq_lo);
    cudaGetSymbolAddress((void**)&p_ak_hi, g_ak_hi);
    cudaGetSymbolAddress((void**)&p_ak_lo, g_ak_lo);
    cudaGetSymbolAddress((void**)&p_av_hi, g_av_hi);
    cudaGetSymbolAddress((void**)&p_av_lo, g_av_lo);
    cudaGetSymbolAddress((void**)&p_ctx_hi, g_ctx_hi);
    cudaGetSymbolAddress((void**)&p_ctx_lo, g_ctx_lo);

    const int WELEM = D_MODEL * D_MODEL;   // 1M
    const int AELEM = M_TOK * D_MODEL;     // 4M

    split_f32_k<<<WELEM / 1024, 256>>>(wq, p_wq_hi, p_wq_lo);
    split_f32_k<<<WELEM / 1024, 256>>>(wk, p_wk_hi, p_wk_lo);
    split_f32_k<<<WELEM / 1024, 256>>>(wv, p_wv_hi, p_wv_lo);
    split_f32_k<<<WELEM / 1024, 256>>>(wo, p_wo_hi, p_wo_lo);
    split_f32_k<<<AELEM / 1024, 256>>>(q,  p_aq_hi, p_aq_lo);
    split_f32_k<<<AELEM / 1024, 256>>>(k,  p_ak_hi, p_ak_lo);
    split_f32_k<<<AELEM / 1024, 256>>>(v,  p_av_hi, p_av_lo);

    dim3 gemm_grid(D_MODEL / BN, M_TOK / BM);   // (8, 32)

    mma_gemm2_k<<<gemm_grid, 256>>>(p_aq_hi, p_aq_lo, p_wq_hi, p_wq_lo, bq, nullptr, 0);
    mma_gemm2_k<<<gemm_grid, 256>>>(p_ak_hi, p_ak_lo, p_wk_hi, p_wk_lo, bk, nullptr, 1);
    mma_gemm2_k<<<gemm_grid, 256>>>(p_av_hi, p_av_lo, p_wv_hi, p_wv_lo, bv, nullptr, 2);

    const int fa_smem = 4 * 64 * FSTR * (int)sizeof(uint16_t);   // 36864
    cudaFuncSetAttribute(flash_mma_k,
                         cudaFuncAttributeMaxDynamicSharedMemorySize, fa_smem);
    flash_mma_k<<<dim3(SEQ / 128, BH), 256, fa_smem>>>();

    mma_gemm2_k<<<gemm_grid, 256>>>(p_ctx_hi, p_ctx_lo, p_wo_hi, p_wo_lo, bo, out, 3);
}

// round 10
// speedup vs baseline: 1.2466x; 1.2466x over previous
#include <cuda_runtime.h>
#include <cuda_bf16.h>
#include <stdint.h>

#define D_MODEL 1024
#define HEADS   16
#define DK      64
#define BATCH   2
#define SEQ     2048
#define M_TOK   (BATCH * SEQ)
#define BH      (BATCH * HEADS)

// ---------------- scratch (static device globals; no runtime alloc) ----------
__device__ uint16_t g_wq_hi[D_MODEL * D_MODEL], g_wq_lo[D_MODEL * D_MODEL];
__device__ uint16_t g_wk_hi[D_MODEL * D_MODEL], g_wk_lo[D_MODEL * D_MODEL];
__device__ uint16_t g_wv_hi[D_MODEL * D_MODEL], g_wv_lo[D_MODEL * D_MODEL];
__device__ uint16_t g_wo_hi[D_MODEL * D_MODEL], g_wo_lo[D_MODEL * D_MODEL];
__device__ uint16_t g_aq_hi[M_TOK * D_MODEL], g_aq_lo[M_TOK * D_MODEL];
__device__ uint16_t g_ak_hi[M_TOK * D_MODEL], g_ak_lo[M_TOK * D_MODEL];
__device__ uint16_t g_av_hi[M_TOK * D_MODEL], g_av_lo[M_TOK * D_MODEL];
// projected: Q,K [bh][s][d] (Q pre-scaled); V^T [bh][d][s]
__device__ uint16_t g_q_hi[BH * SEQ * DK], g_q_lo[BH * SEQ * DK];
__device__ uint16_t g_k_hi[BH * SEQ * DK], g_k_lo[BH * SEQ * DK];
__device__ uint16_t g_vt_hi[BH * DK * SEQ], g_vt_lo[BH * DK * SEQ];
// attention output, split [B,S,D_MODEL]
__device__ uint16_t g_ctx_hi[M_TOK * D_MODEL], g_ctx_lo[M_TOK * D_MODEL];

// ---------------- helpers ----------------------------------------------------
__device__ __forceinline__ uint16_t f2bf_bits(float x) {
    __nv_bfloat16 h = __float2bfloat16(x);
    return *reinterpret_cast<uint16_t*>(&h);
}
__device__ __forceinline__ float bfbits2f(uint16_t b) {
    __nv_bfloat16 h = *reinterpret_cast<__nv_bfloat16*>(&b);
    return __bfloat162float(h);
}
__device__ __forceinline__ void split_bf16(float x, uint16_t& hi, uint16_t& lo) {
    hi = f2bf_bits(x);
    lo = f2bf_bits(x - bfbits2f(hi));
}
__device__ __forceinline__ void split_pack2(float p0, float p1,
                                            uint32_t& hi, uint32_t& lo) {
    uint16_t h0, l0, h1, l1;
    split_bf16(p0, h0, l0);
    split_bf16(p1, h1, l1);
    hi = (uint32_t)h0 | ((uint32_t)h1 << 16);
    lo = (uint32_t)l0 | ((uint32_t)l1 << 16);
}

__device__ __forceinline__ void mma16816(float* c, const uint32_t* a, const uint32_t* b) {
    asm volatile(
        "mma.sync.aligned.m16n8k16.row.col.f32.bf16.bf16.f32 "
        "{%0,%1,%2,%3}, {%4,%5,%6,%7}, {%8,%9}, {%0,%1,%2,%3};"
        : "+f"(c[0]), "+f"(c[1]), "+f"(c[2]), "+f"(c[3])
        : "r"(a[0]), "r"(a[1]), "r"(a[2]), "r"(a[3]), "r"(b[0]), "r"(b[1]));
}
__device__ __forceinline__ void ldmx4(uint32_t& r0, uint32_t& r1,
                                      uint32_t& r2, uint32_t& r3, uint32_t addr) {
    asm volatile("ldmatrix.sync.aligned.m8n8.x4.shared.b16 {%0,%1,%2,%3}, [%4];"
        : "=r"(r0), "=r"(r1), "=r"(r2), "=r"(r3) : "r"(addr));
}
__device__ __forceinline__ uint32_t smem_u32(const void* p) {
    return (uint32_t)__cvta_generic_to_shared(p);
}

// ---------------- batched fp32 -> split bf16 --------------------------------
__global__ __launch_bounds__(256) void split_w_k(
    const float* __restrict__ w0, const float* __restrict__ w1,
    const float* __restrict__ w2, const float* __restrict__ w3)
{
    const float* src;
    uint16_t *hi, *lo;
    switch (blockIdx.y) {
        case 0: src = w0; hi = g_wq_hi; lo = g_wq_lo; break;
        case 1: src = w1; hi = g_wk_hi; lo = g_wk_lo; break;
        case 2: src = w2; hi = g_wv_hi; lo = g_wv_lo; break;
        default: src = w3; hi = g_wo_hi; lo = g_wo_lo; break;
    }
    int i = (blockIdx.x * 256 + threadIdx.x) * 4;
    float4 v = *(const float4*)&src[i];
    ushort4 H, L;
    split_bf16(v.x, H.x, L.x); split_bf16(v.y, H.y, L.y);
    split_bf16(v.z, H.z, L.z); split_bf16(v.w, H.w, L.w);
    *(ushort4*)&hi[i] = H;
    *(ushort4*)&lo[i] = L;
}
__global__ __launch_bounds__(256) void split_a_k(
    const float* __restrict__ a0, const float* __restrict__ a1,
    const float* __restrict__ a2)
{
    const float* src;
    uint16_t *hi, *lo;
    switch (blockIdx.y) {
        case 0: src = a0; hi = g_aq_hi; lo = g_aq_lo; break;
        case 1: src = a1; hi = g_ak_hi; lo = g_ak_lo; break;
        default: src = a2; hi = g_av_hi; lo = g_av_lo; break;
    }
    int i = (blockIdx.x * 256 + threadIdx.x) * 4;
    float4 v = *(const float4*)&src[i];
    ushort4 H, L;
    split_bf16(v.x, H.x, L.x); split_bf16(v.y, H.y, L.y);
    split_bf16(v.z, H.z, L.z); split_bf16(v.w, H.w, L.w);
    *(ushort4*)&hi[i] = H;
    *(ushort4*)&lo[i] = L;
}

// ---------------- split-bf16 tensor GEMM (pre-split, ldmatrix frags) --------
// C = A[M,K] * W[N,K]^T + bias;  C ~= Ah*Wh + Ah*Wl + Al*Wh.
// mode 0: -> g_q (split, *0.125, [bh][s][d]); 1: -> g_k; 2: -> g_vt ([bh][d][s]);
// mode 3: -> Cflat fp32 [M][N]
#define BM  128
#define BN  128
#define BK  32
#define BKP 40

__global__ __launch_bounds__(256, 2) void mma_gemm2_k(
    const uint16_t* __restrict__ Ah, const uint16_t* __restrict__ Al,
    const uint16_t* __restrict__ Wh, const uint16_t* __restrict__ Wl,
    const float* __restrict__ bias, float* __restrict__ Cflat, int mode)
{
    __shared__ uint16_t Ahi[BM][BKP], Alo[BM][BKP];
    __shared__ uint16_t Whi[BN][BKP], Wlo[BN][BKP];

    const int tid  = threadIdx.x;
    const int lane = tid & 31, w = tid >> 5;
    const int wm = w & 1, wn = w >> 1;
    const int g  = lane >> 2, tq = lane & 3;
    const int m0 = blockIdx.y * BM, n0 = blockIdx.x * BN;

    // ldmatrix lane-class bases
    const int lq  = lane & 7, cls = lane >> 3;
    // A: cls0: hi rows+0 col+0 | cls1: hi rows+8 col+0 | cls2: hi rows+0 col+8 | cls3: hi rows+8 col+8
    const uint32_t a_hi_base = smem_u32(&Ahi[(cls & 1) * 8 + lq][(cls >> 1) * 8]);
    const uint32_t a_lo_base = smem_u32(&Alo[(cls & 1) * 8 + lq][(cls >> 1) * 8]);
    // W: cls0: hi col+0 | cls1: hi col+8 | cls2: lo col+0 | cls3: lo col+8 ; rows = n-block + lq
    const uint32_t w_base = (cls < 2)
        ? smem_u32(&Whi[wn * 32 + lq][(cls & 1) * 8])
        : smem_u32(&Wlo[wn * 32 + lq][(cls & 1) * 8]);

    float acc[4][4][4];
#pragma unroll
    for (int mi = 0; mi < 4; mi++)
#pragma unroll
        for (int ni = 0; ni < 4; ni++)
#pragma unroll
            for (int r = 0; r < 4; r++) acc[mi][ni][r] = 0.f;

    for (int kt = 0; kt < D_MODEL; kt += BK) {
        __syncthreads();
#pragma unroll
        for (int l = 0; l < 2; l++) {
            int id  = tid + l * 256;
            int row = id >> 2;
            int c   = (id & 3) << 3;
            size_t asrc = (size_t)(m0 + row) * D_MODEL + kt + c;
            size_t wsrc = (size_t)(n0 + row) * D_MODEL + kt + c;
            *(uint4*)&Ahi[row][c] = *(const uint4*)&Ah[asrc];
            *(uint4*)&Alo[row][c] = *(const uint4*)&Al[asrc];
            *(uint4*)&Whi[row][c] = *(const uint4*)&Wh[wsrc];
            *(uint4*)&Wlo[row][c] = *(const uint4*)&Wl[wsrc];
        }
        __syncthreads();

#pragma unroll
        for (int s = 0; s < 2; s++) {
            uint32_t bhf[4][2], blf[4][2];
#pragma unroll
            for (int ni = 0; ni < 4; ni++) {
                uint32_t addr = w_base + (uint32_t)((ni * 8 * BKP + s * 16) * 2);
                ldmx4(bhf[ni][0], bhf[ni][1], blf[ni][0], blf[ni][1], addr);
            }
#pragma unroll
            for (int mi = 0; mi < 4; mi++) {
                uint32_t moff = (uint32_t)(((wm * 64 + mi * 16) * BKP + s * 16) * 2);
                uint32_t ah[4], al[4];
                ldmx4(ah[0], ah[1], ah[2], ah[3], a_hi_base + moff);
                ldmx4(al[0], al[1], al[2], al[3], a_lo_base + moff);
#pragma unroll
                for (int ni = 0; ni < 4; ni++) {
                    mma16816(acc[mi][ni], ah, bhf[ni]);
                    mma16816(acc[mi][ni], ah, blf[ni]);
                    mma16816(acc[mi][ni], al, bhf[ni]);
                }
            }
        }
    }

    const float sc = (mode == 0) ? 0.125f : 1.0f;

#pragma unroll
    for (int mi = 0; mi < 4; mi++) {
#pragma unroll
        for (int ni = 0; ni < 4; ni++) {
#pragma unroll
            for (int half = 0; half < 2; half++) {
                int m = m0 + wm * 64 + mi * 16 + g + half * 8;
#pragma unroll
                for (int cc = 0; cc < 2; cc++) {
                    int n = n0 + wn * 32 + ni * 8 + tq * 2 + cc;
                    float v = acc[mi][ni][half * 2 + cc] + bias[n];
                    if (mode == 3) {
                        Cflat[(size_t)m * D_MODEL + n] = v;
                    } else {
                        int b_ = m >> 11, ss = m & (SEQ - 1);
                        int h  = n >> 6,  d  = n & 63;
                        int bh = b_ * HEADS + h;
                        uint16_t vh, vl;
                        split_bf16(v * sc, vh, vl);
                        if (mode == 0) {
                            size_t idx = ((size_t)bh * SEQ + ss) * DK + d;
                            g_q_hi[idx] = vh; g_q_lo[idx] = vl;
                        } else if (mode == 1) {
                            size_t idx = ((size_t)bh * SEQ + ss) * DK + d;
                            g_k_hi[idx] = vh; g_k_lo[idx] = vl;
                        } else {
                            size_t idx = ((size_t)bh * DK + d) * SEQ + ss;
                            g_vt_hi[idx] = vh; g_vt_lo[idx] = vl;
                        }
                    }
                }
            }
        }
    }
}

// ---------------- tensor-core flash attention (split bf16, ldmatrix) --------
// 128 threads = 4 warps; warp w owns q rows [w*16, w*16+16) of a 64-row block.
// 64-key tiles. Q staged transiently into the K smem arrays (aliased).
#define FSTR 72

__global__ __launch_bounds__(128, 4) void flash_mma_k()
{
    extern __shared__ uint16_t smu[];
    uint16_t* Khi = smu;                    // [64][FSTR]
    uint16_t* Klo = smu + 64 * FSTR;
    uint16_t* Vhi = smu + 2 * 64 * FSTR;    // V^T tile [d][key]
    uint16_t* Vlo = smu + 3 * 64 * FSTR;
    uint16_t* Qhi = Khi;                    // alias (Q staged before k-loop)
    uint16_t* Qlo = Klo;

    const int tid  = threadIdx.x;
    const int lane = tid & 31, w = tid >> 5;
    const int g = lane >> 2, tq = lane & 3;
    const int bh = blockIdx.y;
    const int b  = bh >> 4, h = bh & 15;
    const int qbase = blockIdx.x * 64;
    const int q0 = w * 16;

    // ldmatrix lane-class bases (shared by K and V: same [row][FSTR] geometry)
    const int lq = lane & 7, cls = lane >> 3;
    const uint32_t k_base = (cls < 2)
        ? smem_u32(&Khi[lq * FSTR + (cls & 1) * 8])
        : smem_u32(&Klo[lq * FSTR + (cls & 1) * 8]);
    const uint32_t v_base = (cls < 2)
        ? smem_u32(&Vhi[lq * FSTR + (cls & 1) * 8])
        : smem_u32(&Vlo[lq * FSTR + (cls & 1) * 8]);

    // stage Q tile (64 rows, hi/lo) into aliased smem
#pragma unroll
    for (int l = 0; l < 4; l++) {
        int id  = tid + l * 128;
        int row = id >> 3;
        int dc  = (id & 7) << 3;
        size_t src = ((size_t)bh * SEQ + qbase + row) * DK + dc;
        *(uint4*)&Qhi[row * FSTR + dc] = *(const uint4*)&g_q_hi[src];
        *(uint4*)&Qlo[row * FSTR + dc] = *(const uint4*)&g_q_lo[src];
    }
    __syncthreads();

    // Q fragments to registers (live across whole k-loop)
    uint32_t aqh[4][4], aql[4][4];
#pragma unroll
    for (int t = 0; t < 4; t++) {
        int c0 = 16 * t + 2 * tq;
        aqh[t][0] = *(const uint32_t*)&Qhi[(q0 + g    ) * FSTR + c0];
        aqh[t][1] = *(const uint32_t*)&Qhi[(q0 + g + 8) * FSTR + c0];
        aqh[t][2] = *(const uint32_t*)&Qhi[(q0 + g    ) * FSTR + c0 + 8];
        aqh[t][3] = *(const uint32_t*)&Qhi[(q0 + g + 8) * FSTR + c0 + 8];
        aql[t][0] = *(const uint32_t*)&Qlo[(q0 + g    ) * FSTR + c0];
        aql[t][1] = *(const uint32_t*)&Qlo[(q0 + g + 8) * FSTR + c0];
        aql[t][2] = *(const uint32_t*)&Qlo[(q0 + g    ) * FSTR + c0 + 8];
        aql[t][3] = *(const uint32_t*)&Qlo[(q0 + g + 8) * FSTR + c0 + 8];
    }

    float m0 = -1e30f, m1 = -1e30f, l0 = 0.f, l1 = 0.f;
    float oacc[8][4];
#pragma unroll
    for (int dj = 0; dj < 8; dj++)
#pragma unroll
        for (int r = 0; r < 4; r++) oacc[dj][r] = 0.f;

    for (int kt = 0; kt < SEQ; kt += 64) {
        __syncthreads();   // Q frag extraction / prev-tile reads done
        // stage K and V^T tiles (hi/lo)
#pragma unroll
        for (int l = 0; l < 4; l++) {
            int id  = tid + l * 128;
            int row = id >> 3;
            int dc  = (id & 7) << 3;
            size_t ksrc = ((size_t)bh * SEQ + kt + row) * DK + dc;
            *(uint4*)&Khi[row * FSTR + dc] = *(const uint4*)&g_k_hi[ksrc];
            *(uint4*)&Klo[row * FSTR + dc] = *(const uint4*)&g_k_lo[ksrc];
            size_t vsrc = ((size_t)bh * DK + row) * SEQ + kt + dc;
            *(uint4*)&Vhi[row * FSTR + dc] = *(const uint4*)&g_vt_hi[vsrc];
            *(uint4*)&Vlo[row * FSTR + dc] = *(const uint4*)&g_vt_lo[vsrc];
        }
        __syncthreads();

        // ---- S = Q.K^T (3-pass split, ldmatrix b-frags) ----
        float sacc[8][4];
#pragma unroll
        for (int j = 0; j < 8; j++)
#pragma unroll
            for (int r = 0; r < 4; r++) sacc[j][r] = 0.f;

#pragma unroll
        for (int j = 0; j < 8; j++) {
            uint32_t joff = (uint32_t)(8 * j * FSTR * 2);
#pragma unroll
            for (int t = 0; t < 4; t++) {
                uint32_t bhf[2], blf[2];
                ldmx4(bhf[0], bhf[1], blf[0], blf[1], k_base + joff + (uint32_t)(t * 32));
                mma16816(sacc[j], aqh[t], bhf);
                mma16816(sacc[j], aqh[t], blf);
                mma16816(sacc[j], aql[t], bhf);
            }
        }

        // ---- online softmax ----
        float mx0 = -1e30f, mx1 = -1e30f;
#pragma unroll
        for (int j = 0; j < 8; j++) {
            mx0 = fmaxf(mx0, fmaxf(sacc[j][0], sacc[j][1]));
            mx1 = fmaxf(mx1, fmaxf(sacc[j][2], sacc[j][3]));
        }
#pragma unroll
        for (int off = 1; off <= 2; off <<= 1) {
            mx0 = fmaxf(mx0, __shfl_xor_sync(0xffffffffu, mx0, off));
            mx1 = fmaxf(mx1, __shfl_xor_sync(0xffffffffu, mx1, off));
        }
        float mn0 = fmaxf(m0, mx0), mn1 = fmaxf(m1, mx1);
        float al0 = __expf(m0 - mn0), al1 = __expf(m1 - mn1);
        m0 = mn0; m1 = mn1;

        float rs0 = 0.f, rs1 = 0.f;
#pragma unroll
        for (int j = 0; j < 8; j++) {
            sacc[j][0] = __expf(sacc[j][0] - mn0);
            sacc[j][1] = __expf(sacc[j][1] - mn0);
            sacc[j][2] = __expf(sacc[j][2] - mn1);
            sacc[j][3] = __expf(sacc[j][3] - mn1);
            rs0 += sacc[j][0] + sacc[j][1];
            rs1 += sacc[j][2] + sacc[j][3];
        }
#pragma unroll
        for (int off = 1; off <= 2; off <<= 1) {
            rs0 += __shfl_xor_sync(0xffffffffu, rs0, off);
            rs1 += __shfl_xor_sync(0xffffffffu, rs1, off);
        }
        l0 = l0 * al0 + rs0;
        l1 = l1 * al1 + rs1;
#pragma unroll
        for (int dj = 0; dj < 8; dj++) {
            oacc[dj][0] *= al0; oacc[dj][1] *= al0;
            oacc[dj][2] *= al1; oacc[dj][3] *= al1;
        }

        // ---- P -> split bf16 A-fragments ----
        uint32_t pah[4][4], pal[4][4];
#pragma unroll
        for (int t = 0; t < 4; t++) {
            split_pack2(sacc[2*t    ][0], sacc[2*t    ][1], pah[t][0], pal[t][0]);
            split_pack2(sacc[2*t    ][2], sacc[2*t    ][3], pah[t][1], pal[t][1]);
            split_pack2(sacc[2*t + 1][0], sacc[2*t + 1][1], pah[t][2], pal[t][2]);
            split_pack2(sacc[2*t + 1][2], sacc[2*t + 1][3], pah[t][3], pal[t][3]);
        }

        // ---- O += P.V (3-pass split, ldmatrix b-frags) ----
#pragma unroll
        for (int dj = 0; dj < 8; dj++) {
            uint32_t joff = (uint32_t)(8 * dj * FSTR * 2);
#pragma unroll
            for (int t = 0; t < 4; t++) {
                uint32_t bhf[2], blf[2];
                ldmx4(bhf[0], bhf[1], blf[0], blf[1], v_base + joff + (uint32_t)(t * 32));
                mma16816(oacc[dj], pah[t], bhf);
                mma16816(oacc[dj], pah[t], blf);
                mma16816(oacc[dj], pal[t], bhf);
            }
        }
    }

    // epilogue: normalize, split, write ctx (split bf16, concat layout)
    float inv0 = 1.f / l0, inv1 = 1.f / l1;
    int s0 = qbase + q0 + g;
    int s1 = s0 + 8;
#pragma unroll
    for (int dj = 0; dj < 8; dj++) {
        int d = h * DK + 8 * dj + 2 * tq;
        uint32_t h0, lo0, h1, lo1;
        split_pack2(oacc[dj][0] * inv0, oacc[dj][1] * inv0, h0, lo0);
        split_pack2(oacc[dj][2] * inv1, oacc[dj][3] * inv1, h1, lo1);
        size_t i0 = (size_t)(b * SEQ + s0) * D_MODEL + d;
        size_t i1 = (size_t)(b * SEQ + s1) * D_MODEL + d;
        *(uint32_t*)&g_ctx_hi[i0] = h0;
        *(uint32_t*)&g_ctx_lo[i0] = lo0;
        *(uint32_t*)&g_ctx_hi[i1] = h1;
        *(uint32_t*)&g_ctx_lo[i1] = lo1;
    }
}

// ---------------- launch ----------------------------------------------------
extern "C" void kernel_launch(void* const* d_in, const int* in_sizes, int n_in,
                              void* d_out, int out_size)
{
    const float* q  = (const float*)d_in[0];
    const float* k  = (const float*)d_in[1];
    const float* v  = (const float*)d_in[2];
    const float* wq = (const float*)d_in[3];
    const float* bq = (const float*)d_in[4];
    const float* wk = (const float*)d_in[5];
    const float* bk = (const float*)d_in[6];
    const float* wv = (const float*)d_in[7];
    const float* bv = (const float*)d_in[8];
    const float* wo = (const float*)d_in[9];
    const float* bo = (const float*)d_in[10];
    float* out = (float*)d_out;

    uint16_t *p_wq_hi, *p_wq_lo, *p_wk_hi, *p_wk_lo, *p_wv_hi, *p_wv_lo;
    uint16_t *p_wo_hi, *p_wo_lo, *p_aq_hi, *p_aq_lo, *p_ak_hi, *p_ak_lo;
    uint16_t *p_av_hi, *p_av_lo, *p_ctx_hi, *p_ctx_lo;
    cudaGetSymbolAddress((void**)&p_wq_hi, g_wq_hi);
    cudaGetSymbolAddress((void**)&p_wq_lo, g_wq_lo);
    cudaGetSymbolAddress((void**)&p_wk_hi, g_wk_hi);
    cudaGetSymbolAddress((void**)&p_wk_lo, g_wk_lo);
    cudaGetSymbolAddress((void**)&p_wv_hi, g_wv_hi);
    cudaGetSymbolAddress((void**)&p_wv_lo, g_wv_lo);
    cudaGetSymbolAddress((void**)&p_wo_hi, g_wo_hi);
    cudaGetSymbolAddress((void**)&p_wo_lo, g_wo_lo);
    cudaGetSymbolAddress((void**)&p_aq_hi, g_aq_hi);
    cudaGetSymbolAddress((void**)&p_aq_lo, g_aq_lo);
    cudaGetSymbolAddress((void**)&p_ak_hi, g_ak_hi);
    cudaGetSymbolAddress((void**)&p_ak_lo, g_ak_lo);
    cudaGetSymbolAddress((void**)&p_av_hi, g_av_hi);
    cudaGetSymbolAddress((void**)&p_av_lo, g_av_lo);
    cudaGetSymbolAddress((void**)&p_ctx_hi, g_ctx_hi);
    cudaGetSymbolAddress((void**)&p_ctx_lo, g_ctx_lo);

    const int WELEM = D_MODEL * D_MODEL;   // 1M
    const int AELEM = M_TOK * D_MODEL;     // 4M

    split_w_k<<<dim3(WELEM / 1024, 4), 256>>>(wq, wk, wv, wo);
    split_a_k<<<dim3(AELEM / 1024, 3), 256>>>(q, k, v);

    dim3 gemm_grid(D_MODEL / BN, M_TOK / BM);   // (8, 32)

    mma_gemm2_k<<<gemm_grid, 256>>>(p_aq_hi, p_aq_lo, p_wq_hi, p_wq_lo, bq, nullptr, 0);
    mma_gemm2_k<<<gemm_grid, 256>>>(p_ak_hi, p_ak_lo, p_wk_hi, p_wk_lo, bk, nullptr, 1);
    mma_gemm2_k<<<gemm_grid, 256>>>(p_av_hi, p_av_lo, p_wv_hi, p_wv_lo, bv, nullptr, 2);

    const int fa_smem = 4 * 64 * FSTR * (int)sizeof(uint16_t);   // 36864
    cudaFuncSetAttribute(flash_mma_k,
                         cudaFuncAttributeMaxDynamicSharedMemorySize, fa_smem);
    flash_mma_k<<<dim3(SEQ / 64, BH), 128, fa_smem>>>();

    mma_gemm2_k<<<gemm_grid, 256>>>(p_ctx_hi, p_ctx_lo, p_wo_hi, p_wo_lo, bo, out, 3);
}

// round 13
// speedup vs baseline: 1.2879x; 1.0331x over previous
#include <cuda_runtime.h>
#include <cuda_bf16.h>
#include <stdint.h>

#define D_MODEL 1024
#define HEADS   16
#define DK      64
#define BATCH   2
#define SEQ     2048
#define M_TOK   (BATCH * SEQ)
#define BH      (BATCH * HEADS)

// ---------------- scratch (static device globals; no runtime alloc) ----------
__device__ uint16_t g_wq_hi[D_MODEL * D_MODEL], g_wq_lo[D_MODEL * D_MODEL];
__device__ uint16_t g_wk_hi[D_MODEL * D_MODEL], g_wk_lo[D_MODEL * D_MODEL];
__device__ uint16_t g_wv_hi[D_MODEL * D_MODEL], g_wv_lo[D_MODEL * D_MODEL];
__device__ uint16_t g_wo_hi[D_MODEL * D_MODEL], g_wo_lo[D_MODEL * D_MODEL];
__device__ uint16_t g_aq_hi[M_TOK * D_MODEL], g_aq_lo[M_TOK * D_MODEL];
__device__ uint16_t g_ak_hi[M_TOK * D_MODEL], g_ak_lo[M_TOK * D_MODEL];
__device__ uint16_t g_av_hi[M_TOK * D_MODEL], g_av_lo[M_TOK * D_MODEL];
// projected: Q,K [bh][s][d] (Q pre-scaled); V^T [bh][d][s]
__device__ uint16_t g_q_hi[BH * SEQ * DK], g_q_lo[BH * SEQ * DK];
__device__ uint16_t g_k_hi[BH * SEQ * DK], g_k_lo[BH * SEQ * DK];
__device__ uint16_t g_vt_hi[BH * DK * SEQ], g_vt_lo[BH * DK * SEQ];
// attention output, split [B,S,D_MODEL]
__device__ uint16_t g_ctx_hi[M_TOK * D_MODEL], g_ctx_lo[M_TOK * D_MODEL];

// ---------------- helpers ----------------------------------------------------
__device__ __forceinline__ uint16_t f2bf_bits(float x) {
    __nv_bfloat16 h = __float2bfloat16(x);
    return *reinterpret_cast<uint16_t*>(&h);
}
__device__ __forceinline__ float bfbits2f(uint16_t b) {
    __nv_bfloat16 h = *reinterpret_cast<__nv_bfloat16*>(&b);
    return __bfloat162float(h);
}
__device__ __forceinline__ void split_bf16(float x, uint16_t& hi, uint16_t& lo) {
    hi = f2bf_bits(x);
    lo = f2bf_bits(x - bfbits2f(hi));
}
__device__ __forceinline__ void split_pack2(float p0, float p1,
                                            uint32_t& hi, uint32_t& lo) {
    uint16_t h0, l0, h1, l1;
    split_bf16(p0, h0, l0);
    split_bf16(p1, h1, l1);
    hi = (uint32_t)h0 | ((uint32_t)h1 << 16);
    lo = (uint32_t)l0 | ((uint32_t)l1 << 16);
}

__device__ __forceinline__ void mma16816(float* c, const uint32_t* a, const uint32_t* b) {
    asm volatile(
        "mma.sync.aligned.m16n8k16.row.col.f32.bf16.bf16.f32 "
        "{%0,%1,%2,%3}, {%4,%5,%6,%7}, {%8,%9}, {%0,%1,%2,%3};"
        : "+f"(c[0]), "+f"(c[1]), "+f"(c[2]), "+f"(c[3])
        : "r"(a[0]), "r"(a[1]), "r"(a[2]), "r"(a[3]), "r"(b[0]), "r"(b[1]));
}
__device__ __forceinline__ void ldmx4(uint32_t& r0, uint32_t& r1,
                                      uint32_t& r2, uint32_t& r3, uint32_t addr) {
    asm volatile("ldmatrix.sync.aligned.m8n8.x4.shared.b16 {%0,%1,%2,%3}, [%4];"
        : "=r"(r0), "=r"(r1), "=r"(r2), "=r"(r3) : "r"(addr));
}
__device__ __forceinline__ uint32_t smem_u32(const void* p) {
    return (uint32_t)__cvta_generic_to_shared(p);
}
#define CP_ASYNC16(dst, src) \
    asm volatile("cp.async.cg.shared.global [%0], [%1], 16;" :: "r"(dst), "l"(src))
#define CP_COMMIT() asm volatile("cp.async.commit_group;")
#define CP_WAIT0()  asm volatile("cp.async.wait_group 0;")
#define CP_WAIT1()  asm volatile("cp.async.wait_group 1;")

// ---------------- batched fp32 -> split bf16 --------------------------------
__global__ __launch_bounds__(256) void split_w_k(
    const float* __restrict__ w0, const float* __restrict__ w1,
    const float* __restrict__ w2, const float* __restrict__ w3)
{
    const float* src;
    uint16_t *hi, *lo;
    switch (blockIdx.y) {
        case 0: src = w0; hi = g_wq_hi; lo = g_wq_lo; break;
        case 1: src = w1; hi = g_wk_hi; lo = g_wk_lo; break;
        case 2: src = w2; hi = g_wv_hi; lo = g_wv_lo; break;
        default: src = w3; hi = g_wo_hi; lo = g_wo_lo; break;
    }
    int i = (blockIdx.x * 256 + threadIdx.x) * 4;
    float4 v = *(const float4*)&src[i];
    ushort4 H, L;
    split_bf16(v.x, H.x, L.x); split_bf16(v.y, H.y, L.y);
    split_bf16(v.z, H.z, L.z); split_bf16(v.w, H.w, L.w);
    *(ushort4*)&hi[i] = H;
    *(ushort4*)&lo[i] = L;
}
__global__ __launch_bounds__(256) void split_a_k(
    const float* __restrict__ a0, const float* __restrict__ a1,
    const float* __restrict__ a2)
{
    const float* src;
    uint16_t *hi, *lo;
    switch (blockIdx.y) {
        case 0: src = a0; hi = g_aq_hi; lo = g_aq_lo; break;
        case 1: src = a1; hi = g_ak_hi; lo = g_ak_lo; break;
        default: src = a2; hi = g_av_hi; lo = g_av_lo; break;
    }
    int i = (blockIdx.x * 256 + threadIdx.x) * 4;
    float4 v = *(const float4*)&src[i];
    ushort4 H, L;
    split_bf16(v.x, H.x, L.x); split_bf16(v.y, H.y, L.y);
    split_bf16(v.z, H.z, L.z); split_bf16(v.w, H.w, L.w);
    *(ushort4*)&hi[i] = H;
    *(ushort4*)&lo[i] = L;
}

// ---------------- split-bf16 tensor GEMM v3 (cp.async double-buffered) ------
// C = A[M,K] * W[N,K]^T + bias;  C ~= Ah*Wh + Ah*Wl + Al*Wh.
// mode = mode_base + blockIdx.z:
//   0 -> g_q (split, *0.125, [bh][s][d]); 1 -> g_k; 2 -> g_vt ([bh][d][s]);
//   3 -> Cflat fp32 [M][N]  (A = g_ctx, W = g_wo)
#define BM  128
#define BN  128
#define BK  32
#define BKP 40
// stage layout, ELEMENT offsets (each array BM*BKP = 5120 elems = 10240 B):
//   Ahi@0  Alo@5120  Whi@10240  Wlo@15360 ; stage total 20480 elems = 40960 B
#define ST_ELEMS 20480
#define ST_BYTES 40960
#define OFF_ALO  5120
#define OFF_WHI  10240
#define OFF_WLO  15360

__global__ __launch_bounds__(256, 2) void mma_gemm3_k(
    const float* __restrict__ bq_, const float* __restrict__ bk_,
    const float* __restrict__ bv_, const float* __restrict__ bo_,
    float* __restrict__ Cflat, int mode_base)
{
    extern __shared__ uint16_t gsm[];
    const uint32_t smbase = smem_u32(gsm);

    const int mode = mode_base + blockIdx.z;
    const uint16_t *Ah, *Al, *Wh, *Wl;
    const float* bias;
    if (mode == 0)      { Ah = g_aq_hi;  Al = g_aq_lo;  Wh = g_wq_hi; Wl = g_wq_lo; bias = bq_; }
    else if (mode == 1) { Ah = g_ak_hi;  Al = g_ak_lo;  Wh = g_wk_hi; Wl = g_wk_lo; bias = bk_; }
    else if (mode == 2) { Ah = g_av_hi;  Al = g_av_lo;  Wh = g_wv_hi; Wl = g_wv_lo; bias = bv_; }
    else                { Ah = g_ctx_hi; Al = g_ctx_lo; Wh = g_wo_hi; Wl = g_wo_lo; bias = bo_; }

    const int tid  = threadIdx.x;
    const int lane = tid & 31, w = tid >> 5;
    const int wm = w & 1, wn = w >> 1;
    const int g  = lane >> 2, tq = lane & 3;
    const int m0 = blockIdx.y * BM, n0 = blockIdx.x * BN;

    // ldmatrix lane-class byte offsets within a stage
    const int lq  = lane & 7, cls = lane >> 3;
    const uint32_t a_hi_off = (uint32_t)((((cls & 1) * 8 + lq) * BKP + (cls >> 1) * 8) * 2);
    const uint32_t a_lo_off = a_hi_off + OFF_ALO * 2;
    const uint32_t w_off = (uint32_t)(((wn * 32 + lq) * BKP + (cls & 1) * 8) * 2)
                         + (uint32_t)((cls < 2 ? OFF_WHI : OFF_WLO) * 2);

    // staging: per thread 2 rows x 4 arrays, 16B each
    const int st_row0 = tid >> 2;          // id = tid
    const int st_c0   = (tid & 3) << 3;
    const int st_row1 = (tid + 256) >> 2;  // id = tid + 256
    const int st_c1   = ((tid + 256) & 3) << 3;
    const uint32_t so0 = (uint32_t)((st_row0 * BKP + st_c0) * 2);
    const uint32_t so1 = (uint32_t)((st_row1 * BKP + st_c1) * 2);

    float acc[4][4][4];
#pragma unroll
    for (int mi = 0; mi < 4; mi++)
#pragma unroll
        for (int ni = 0; ni < 4; ni++)
#pragma unroll
            for (int r = 0; r < 4; r++) acc[mi][ni][r] = 0.f;

    auto prefetch = [&](int kt, int st) {
        uint32_t sb = smbase + (uint32_t)st * ST_BYTES;
        size_t a0 = (size_t)(m0 + st_row0) * D_MODEL + kt + st_c0;
        size_t w0s = (size_t)(n0 + st_row0) * D_MODEL + kt + st_c0;
        CP_ASYNC16(sb + so0,                &Ah[a0]);
        CP_ASYNC16(sb + so0 + OFF_ALO * 2,  &Al[a0]);
        CP_ASYNC16(sb + so0 + OFF_WHI * 2,  &Wh[w0s]);
        CP_ASYNC16(sb + so0 + OFF_WLO * 2,  &Wl[w0s]);
        size_t a1 = (size_t)(m0 + st_row1) * D_MODEL + kt + st_c1;
        size_t w1s = (size_t)(n0 + st_row1) * D_MODEL + kt + st_c1;
        CP_ASYNC16(sb + so1,                &Ah[a1]);
        CP_ASYNC16(sb + so1 + OFF_ALO * 2,  &Al[a1]);
        CP_ASYNC16(sb + so1 + OFF_WHI * 2,  &Wh[w1s]);
        CP_ASYNC16(sb + so1 + OFF_WLO * 2,  &Wl[w1s]);
    };

    const int NT = D_MODEL / BK;   // 32
    prefetch(0, 0);
    CP_COMMIT();

    for (int t = 0; t < NT; t++) {
        if (t + 1 < NT) {
            prefetch((t + 1) * BK, (t + 1) & 1);
            CP_COMMIT();
            CP_WAIT1();
        } else {
            CP_WAIT0();
        }
        __syncthreads();

        const uint32_t sb = smbase + (uint32_t)(t & 1) * ST_BYTES;
#pragma unroll
        for (int s = 0; s < 2; s++) {
            uint32_t bhf[4][2], blf[4][2];
#pragma unroll
            for (int ni = 0; ni < 4; ni++) {
                uint32_t addr = sb + w_off + (uint32_t)((ni * 8 * BKP + s * 16) * 2);
                ldmx4(bhf[ni][0], bhf[ni][1], blf[ni][0], blf[ni][1], addr);
            }
#pragma unroll
            for (int mi = 0; mi < 4; mi++) {
                uint32_t moff = (uint32_t)(((wm * 64 + mi * 16) * BKP + s * 16) * 2);
                uint32_t ah[4], al[4];
                ldmx4(ah[0], ah[1], ah[2], ah[3], sb + a_hi_off + moff);
                ldmx4(al[0], al[1], al[2], al[3], sb + a_lo_off + moff);
#pragma unroll
                for (int ni = 0; ni < 4; ni++) {
                    mma16816(acc[mi][ni], ah, bhf[ni]);
                    mma16816(acc[mi][ni], ah, blf[ni]);
                    mma16816(acc[mi][ni], al, bhf[ni]);
                }
            }
        }
        __syncthreads();
    }

    const float sc = (mode == 0) ? 0.125f : 1.0f;

#pragma unroll
    for (int mi = 0; mi < 4; mi++) {
#pragma unroll
        for (int ni = 0; ni < 4; ni++) {
#pragma unroll
            for (int half = 0; half < 2; half++) {
                int m = m0 + wm * 64 + mi * 16 + g + half * 8;
#pragma unroll
                for (int cc = 0; cc < 2; cc++) {
                    int n = n0 + wn * 32 + ni * 8 + tq * 2 + cc;
                    float v = acc[mi][ni][half * 2 + cc] + bias[n];
                    if (mode == 3) {
                        Cflat[(size_t)m * D_MODEL + n] = v;
                    } else {
                        int b_ = m >> 11, ss = m & (SEQ - 1);
                        int h  = n >> 6,  d  = n & 63;
                        int bh = b_ * HEADS + h;
                        uint16_t vh, vl;
                        split_bf16(v * sc, vh, vl);
                        if (mode == 0) {
                            size_t idx = ((size_t)bh * SEQ + ss) * DK + d;
                            g_q_hi[idx] = vh; g_q_lo[idx] = vl;
                        } else if (mode == 1) {
                            size_t idx = ((size_t)bh * SEQ + ss) * DK + d;
                            g_k_hi[idx] = vh; g_k_lo[idx] = vl;
                        } else {
                            size_t idx = ((size_t)bh * DK + d) * SEQ + ss;
                            g_vt_hi[idx] = vh; g_vt_lo[idx] = vl;
                        }
                    }
                }
            }
        }
    }
}

// ---------------- tensor-core flash attention (split bf16, ldmatrix) --------
// 128 threads = 4 warps; warp w owns q rows [w*16, w*16+16) of a 64-row block.
// 64-key tiles. Q staged transiently into the K smem arrays (aliased).
#define FSTR 72

__global__ __launch_bounds__(128, 4) void flash_mma_k()
{
    extern __shared__ uint16_t smu[];
    uint16_t* Khi = smu;                    // [64][FSTR]
    uint16_t* Klo = smu + 64 * FSTR;
    uint16_t* Vhi = smu + 2 * 64 * FSTR;    // V^T tile [d][key]
    uint16_t* Vlo = smu + 3 * 64 * FSTR;
    uint16_t* Qhi = Khi;                    // alias (Q staged before k-loop)
    uint16_t* Qlo = Klo;

    const int tid  = threadIdx.x;
    const int lane = tid & 31, w = tid >> 5;
    const int g = lane >> 2, tq = lane & 3;
    const int bh = blockIdx.y;
    const int b  = bh >> 4, h = bh & 15;
    const int qbase = blockIdx.x * 64;
    const int q0 = w * 16;

    const int lq = lane & 7, cls = lane >> 3;
    const uint32_t k_base = (cls < 2)
        ? smem_u32(&Khi[lq * FSTR + (cls & 1) * 8])
        : smem_u32(&Klo[lq * FSTR + (cls & 1) * 8]);
    const uint32_t v_base = (cls < 2)
        ? smem_u32(&Vhi[lq * FSTR + (cls & 1) * 8])
        : smem_u32(&Vlo[lq * FSTR + (cls & 1) * 8]);

    // stage Q tile (cp.async)
#pragma unroll
    for (int l = 0; l < 4; l++) {
        int id  = tid + l * 128;
        int row = id >> 3;
        int dc  = (id & 7) << 3;
        size_t src = ((size_t)bh * SEQ + qbase + row) * DK + dc;
        CP_ASYNC16(smem_u32(&Qhi[row * FSTR + dc]), &g_q_hi[src]);
        CP_ASYNC16(smem_u32(&Qlo[row * FSTR + dc]), &g_q_lo[src]);
    }
    CP_COMMIT();
    CP_WAIT0();
    __syncthreads();

    // Q fragments to registers (live across whole k-loop)
    uint32_t aqh[4][4], aql[4][4];
#pragma unroll
    for (int t = 0; t < 4; t++) {
        int c0 = 16 * t + 2 * tq;
        aqh[t][0] = *(const uint32_t*)&Qhi[(q0 + g    ) * FSTR + c0];
        aqh[t][1] = *(const uint32_t*)&Qhi[(q0 + g + 8) * FSTR + c0];
        aqh[t][2] = *(const uint32_t*)&Qhi[(q0 + g    ) * FSTR + c0 + 8];
        aqh[t][3] = *(const uint32_t*)&Qhi[(q0 + g + 8) * FSTR + c0 + 8];
        aql[t][0] = *(const uint32_t*)&Qlo[(q0 + g    ) * FSTR + c0];
        aql[t][1] = *(const uint32_t*)&Qlo[(q0 + g + 8) * FSTR + c0];
        aql[t][2] = *(const uint32_t*)&Qlo[(q0 + g    ) * FSTR + c0 + 8];
        aql[t][3] = *(const uint32_t*)&Qlo[(q0 + g + 8) * FSTR + c0 + 8];
    }

    float m0 = -1e30f, m1 = -1e30f, l0 = 0.f, l1 = 0.f;
    float oacc[8][4];
#pragma unroll
    for (int dj = 0; dj < 8; dj++)
#pragma unroll
        for (int r = 0; r < 4; r++) oacc[dj][r] = 0.f;

    for (int kt = 0; kt < SEQ; kt += 64) {
        __syncthreads();   // Q frag extraction / prev-tile reads done
        // stage K and V^T tiles (cp.async)
#pragma unroll
        for (int l = 0; l < 4; l++) {
            int id  = tid + l * 128;
            int row = id >> 3;
            int dc  = (id & 7) << 3;
            size_t ksrc = ((size_t)bh * SEQ + kt + row) * DK + dc;
            CP_ASYNC16(smem_u32(&Khi[row * FSTR + dc]), &g_k_hi[ksrc]);
            CP_ASYNC16(smem_u32(&Klo[row * FSTR + dc]), &g_k_lo[ksrc]);
            size_t vsrc = ((size_t)bh * DK + row) * SEQ + kt + dc;
            CP_ASYNC16(smem_u32(&Vhi[row * FSTR + dc]), &g_vt_hi[vsrc]);
            CP_ASYNC16(smem_u32(&Vlo[row * FSTR + dc]), &g_vt_lo[vsrc]);
        }
        CP_COMMIT();
        CP_WAIT0();
        __syncthreads();

        // ---- S = Q.K^T (3-pass split, ldmatrix b-frags) ----
        float sacc[8][4];
#pragma unroll
        for (int j = 0; j < 8; j++)
#pragma unroll
            for (int r = 0; r < 4; r++) sacc[j][r] = 0.f;

#pragma unroll
        for (int j = 0; j < 8; j++) {
            uint32_t joff = (uint32_t)(8 * j * FSTR * 2);
#pragma unroll
            for (int t = 0; t < 4; t++) {
                uint32_t bhf[2], blf[2];
                ldmx4(bhf[0], bhf[1], blf[0], blf[1], k_base + joff + (uint32_t)(t * 32));
                mma16816(sacc[j], aqh[t], bhf);
                mma16816(sacc[j], aqh[t], blf);
                mma16816(sacc[j], aql[t], bhf);
            }
        }

        // ---- online softmax ----
        float mx0 = -1e30f, mx1 = -1e30f;
#pragma unroll
        for (int j = 0; j < 8; j++) {
            mx0 = fmaxf(mx0, fmaxf(sacc[j][0], sacc[j][1]));
            mx1 = fmaxf(mx1, fmaxf(sacc[j][2], sacc[j][3]));
        }
#pragma unroll
        for (int off = 1; off <= 2; off <<= 1) {
            mx0 = fmaxf(mx0, __shfl_xor_sync(0xffffffffu, mx0, off));
            mx1 = fmaxf(mx1, __shfl_xor_sync(0xffffffffu, mx1, off));
        }
        float mn0 = fmaxf(m0, mx0), mn1 = fmaxf(m1, mx1);
        float al0 = __expf(m0 - mn0), al1 = __expf(m1 - mn1);
        m0 = mn0; m1 = mn1;

        float rs0 = 0.f, rs1 = 0.f;
#pragma unroll
        for (int j = 0; j < 8; j++) {
            sacc[j][0] = __expf(sacc[j][0] - mn0);
            sacc[j][1] = __expf(sacc[j][1] - mn0);
            sacc[j][2] = __expf(sacc[j][2] - mn1);
            sacc[j][3] = __expf(sacc[j][3] - mn1);
            rs0 += sacc[j][0] + sacc[j][1];
            rs1 += sacc[j][2] + sacc[j][3];
        }
#pragma unroll
        for (int off = 1; off <= 2; off <<= 1) {
            rs0 += __shfl_xor_sync(0xffffffffu, rs0, off);
            rs1 += __shfl_xor_sync(0xffffffffu, rs1, off);
        }
        l0 = l0 * al0 + rs0;
        l1 = l1 * al1 + rs1;
#pragma unroll
        for (int dj = 0; dj < 8; dj++) {
            oacc[dj][0] *= al0; oacc[dj][1] *= al0;
            oacc[dj][2] *= al1; oacc[dj][3] *= al1;
        }

        // ---- P -> split bf16 A-fragments ----
        uint32_t pah[4][4], pal[4][4];
#pragma unroll
        for (int t = 0; t < 4; t++) {
            split_pack2(sacc[2*t    ][0], sacc[2*t    ][1], pah[t][0], pal[t][0]);
            split_pack2(sacc[2*t    ][2], sacc[2*t    ][3], pah[t][1], pal[t][1]);
            split_pack2(sacc[2*t + 1][0], sacc[2*t + 1][1], pah[t][2], pal[t][2]);
            split_pack2(sacc[2*t + 1][2], sacc[2*t + 1][3], pah[t][3], pal[t][3]);
        }

        // ---- O += P.V (3-pass split, ldmatrix b-frags) ----
#pragma unroll
        for (int dj = 0; dj < 8; dj++) {
            uint32_t joff = (uint32_t)(8 * dj * FSTR * 2);
#pragma unroll
            for (int t = 0; t < 4; t++) {
                uint32_t bhf[2], blf[2];
                ldmx4(bhf[0], bhf[1], blf[0], blf[1], v_base + joff + (uint32_t)(t * 32));
                mma16816(oacc[dj], pah[t], bhf);
                mma16816(oacc[dj], pah[t], blf);
                mma16816(oacc[dj], pal[t], bhf);
            }
        }
    }

    // epilogue: normalize, split, write ctx (split bf16, concat layout)
    float inv0 = 1.f / l0, inv1 = 1.f / l1;
    int s0 = qbase + q0 + g;
    int s1 = s0 + 8;
#pragma unroll
    for (int dj = 0; dj < 8; dj++) {
        int d = h * DK + 8 * dj + 2 * tq;
        uint32_t h0, lo0, h1, lo1;
        split_pack2(oacc[dj][0] * inv0, oacc[dj][1] * inv0, h0, lo0);
        split_pack2(oacc[dj][2] * inv1, oacc[dj][3] * inv1, h1, lo1);
        size_t i0 = (size_t)(b * SEQ + s0) * D_MODEL + d;
        size_t i1 = (size_t)(b * SEQ + s1) * D_MODEL + d;
        *(uint32_t*)&g_ctx_hi[i0] = h0;
        *(uint32_t*)&g_ctx_lo[i0] = lo0;
        *(uint32_t*)&g_ctx_hi[i1] = h1;
        *(uint32_t*)&g_ctx_lo[i1] = lo1;
    }
}

// ---------------- launch ----------------------------------------------------
extern "C" void kernel_launch(void* const* d_in, const int* in_sizes, int n_in,
                              void* d_out, int out_size)
{
    const float* q  = (const float*)d_in[0];
    const float* k  = (const float*)d_in[1];
    const float* v  = (const float*)d_in[2];
    const float* wq = (const float*)d_in[3];
    const float* bq = (const float*)d_in[4];
    const float* wk = (const float*)d_in[5];
    const float* bk = (const float*)d_in[6];
    const float* wv = (const float*)d_in[7];
    const float* bv = (const float*)d_in[8];
    const float* wo = (const float*)d_in[9];
    const float* bo = (const float*)d_in[10];
    float* out = (float*)d_out;

    const int WELEM = D_MODEL * D_MODEL;   // 1M
    const int AELEM = M_TOK * D_MODEL;     // 4M

    split_w_k<<<dim3(WELEM / 1024, 4), 256>>>(wq, wk, wv, wo);
    split_a_k<<<dim3(AELEM / 1024, 3), 256>>>(q, k, v);

    const int gemm_smem = 2 * ST_BYTES;    // 81920
    cudaFuncSetAttribute(mma_gemm3_k,
                         cudaFuncAttributeMaxDynamicSharedMemorySize, gemm_smem);

    // fused Q/K/V projections: grid.z selects mode
    mma_gemm3_k<<<dim3(D_MODEL / BN, M_TOK / BM, 3), 256, gemm_smem>>>(
        bq, bk, bv, bo, nullptr, 0);

    const int fa_smem = 4 * 64 * FSTR * (int)sizeof(uint16_t);   // 36864
    cudaFuncSetAttribute(flash_mma_k,
                         cudaFuncAttributeMaxDynamicSharedMemorySize, fa_smem);
    flash_mma_k<<<dim3(SEQ / 64, BH), 128, fa_smem>>>();

    // output projection
    mma_gemm3_k<<<dim3(D_MODEL / BN, M_TOK / BM, 1), 256, gemm_smem>>>(
        bq, bk, bv, bo, out, 3);
}

// round 14
// speedup vs baseline: 1.3280x; 1.0311x over previous
#include <cuda_runtime.h>
#include <cuda_bf16.h>
#include <stdint.h>

#define D_MODEL 1024
#define HEADS   16
#define DK      64
#define BATCH   2
#define SEQ     2048
#define M_TOK   (BATCH * SEQ)
#define BH      (BATCH * HEADS)

// ---------------- scratch (static device globals; no runtime alloc) ----------
__device__ uint16_t g_wq_hi[D_MODEL * D_MODEL], g_wq_lo[D_MODEL * D_MODEL];
__device__ uint16_t g_wk_hi[D_MODEL * D_MODEL], g_wk_lo[D_MODEL * D_MODEL];
__device__ uint16_t g_wv_hi[D_MODEL * D_MODEL], g_wv_lo[D_MODEL * D_MODEL];
__device__ uint16_t g_wo_hi[D_MODEL * D_MODEL], g_wo_lo[D_MODEL * D_MODEL];
__device__ uint16_t g_aq_hi[M_TOK * D_MODEL], g_aq_lo[M_TOK * D_MODEL];
__device__ uint16_t g_ak_hi[M_TOK * D_MODEL], g_ak_lo[M_TOK * D_MODEL];
__device__ uint16_t g_av_hi[M_TOK * D_MODEL], g_av_lo[M_TOK * D_MODEL];
// projected: Q,K [bh][s][d] (Q pre-scaled); V^T [bh][d][s]
__device__ uint16_t g_q_hi[BH * SEQ * DK], g_q_lo[BH * SEQ * DK];
__device__ uint16_t g_k_hi[BH * SEQ * DK], g_k_lo[BH * SEQ * DK];
__device__ uint16_t g_vt_hi[BH * DK * SEQ], g_vt_lo[BH * DK * SEQ];
// attention output, split [B,S,D_MODEL]
__device__ uint16_t g_ctx_hi[M_TOK * D_MODEL], g_ctx_lo[M_TOK * D_MODEL];

// ---------------- helpers ----------------------------------------------------
__device__ __forceinline__ uint16_t f2bf_bits(float x) {
    __nv_bfloat16 h = __float2bfloat16(x);
    return *reinterpret_cast<uint16_t*>(&h);
}
__device__ __forceinline__ float bfbits2f(uint16_t b) {
    __nv_bfloat16 h = *reinterpret_cast<__nv_bfloat16*>(&b);
    return __bfloat162float(h);
}
__device__ __forceinline__ void split_bf16(float x, uint16_t& hi, uint16_t& lo) {
    hi = f2bf_bits(x);
    lo = f2bf_bits(x - bfbits2f(hi));
}
__device__ __forceinline__ void split_pack2(float p0, float p1,
                                            uint32_t& hi, uint32_t& lo) {
    uint16_t h0, l0, h1, l1;
    split_bf16(p0, h0, l0);
    split_bf16(p1, h1, l1);
    hi = (uint32_t)h0 | ((uint32_t)h1 << 16);
    lo = (uint32_t)l0 | ((uint32_t)l1 << 16);
}

__device__ __forceinline__ void mma16816(float* c, const uint32_t* a, const uint32_t* b) {
    asm volatile(
        "mma.sync.aligned.m16n8k16.row.col.f32.bf16.bf16.f32 "
        "{%0,%1,%2,%3}, {%4,%5,%6,%7}, {%8,%9}, {%0,%1,%2,%3};"
        : "+f"(c[0]), "+f"(c[1]), "+f"(c[2]), "+f"(c[3])
        : "r"(a[0]), "r"(a[1]), "r"(a[2]), "r"(a[3]), "r"(b[0]), "r"(b[1]));
}
__device__ __forceinline__ void ldmx4(uint32_t& r0, uint32_t& r1,
                                      uint32_t& r2, uint32_t& r3, uint32_t addr) {
    asm volatile("ldmatrix.sync.aligned.m8n8.x4.shared.b16 {%0,%1,%2,%3}, [%4];"
        : "=r"(r0), "=r"(r1), "=r"(r2), "=r"(r3) : "r"(addr));
}
__device__ __forceinline__ uint32_t smem_u32(const void* p) {
    return (uint32_t)__cvta_generic_to_shared(p);
}
#define CP_ASYNC16(dst, src) \
    asm volatile("cp.async.cg.shared.global [%0], [%1], 16;" :: "r"(dst), "l"(src))
#define CP_COMMIT() asm volatile("cp.async.commit_group;")
#define CP_WAIT0()  asm volatile("cp.async.wait_group 0;")
#define CP_WAIT1()  asm volatile("cp.async.wait_group 1;")

// ---------------- batched fp32 -> split bf16 --------------------------------
__global__ __launch_bounds__(256) void split_w_k(
    const float* __restrict__ w0, const float* __restrict__ w1,
    const float* __restrict__ w2, const float* __restrict__ w3)
{
    const float* src;
    uint16_t *hi, *lo;
    switch (blockIdx.y) {
        case 0: src = w0; hi = g_wq_hi; lo = g_wq_lo; break;
        case 1: src = w1; hi = g_wk_hi; lo = g_wk_lo; break;
        case 2: src = w2; hi = g_wv_hi; lo = g_wv_lo; break;
        default: src = w3; hi = g_wo_hi; lo = g_wo_lo; break;
    }
    int i = (blockIdx.x * 256 + threadIdx.x) * 4;
    float4 v = *(const float4*)&src[i];
    ushort4 H, L;
    split_bf16(v.x, H.x, L.x); split_bf16(v.y, H.y, L.y);
    split_bf16(v.z, H.z, L.z); split_bf16(v.w, H.w, L.w);
    *(ushort4*)&hi[i] = H;
    *(ushort4*)&lo[i] = L;
}
__global__ __launch_bounds__(256) void split_a_k(
    const float* __restrict__ a0, const float* __restrict__ a1,
    const float* __restrict__ a2)
{
    const float* src;
    uint16_t *hi, *lo;
    switch (blockIdx.y) {
        case 0: src = a0; hi = g_aq_hi; lo = g_aq_lo; break;
        case 1: src = a1; hi = g_ak_hi; lo = g_ak_lo; break;
        default: src = a2; hi = g_av_hi; lo = g_av_lo; break;
    }
    int i = (blockIdx.x * 256 + threadIdx.x) * 4;
    float4 v = *(const float4*)&src[i];
    ushort4 H, L;
    split_bf16(v.x, H.x, L.x); split_bf16(v.y, H.y, L.y);
    split_bf16(v.z, H.z, L.z); split_bf16(v.w, H.w, L.w);
    *(ushort4*)&hi[i] = H;
    *(ushort4*)&lo[i] = L;
}

// ---------------- split-bf16 tensor GEMM v3 (cp.async double-buffered) ------
#define BM  128
#define BN  128
#define BK  32
#define BKP 40
// stage layout, ELEMENT offsets (each array BM*BKP = 5120 elems = 10240 B):
//   Ahi@0  Alo@5120  Whi@10240  Wlo@15360 ; stage total 20480 elems = 40960 B
#define ST_BYTES 40960
#define OFF_ALO  5120
#define OFF_WHI  10240
#define OFF_WLO  15360

__global__ __launch_bounds__(256, 2) void mma_gemm3_k(
    const float* __restrict__ bq_, const float* __restrict__ bk_,
    const float* __restrict__ bv_, const float* __restrict__ bo_,
    float* __restrict__ Cflat, int mode_base)
{
    extern __shared__ uint16_t gsm[];
    const uint32_t smbase = smem_u32(gsm);

    const int mode = mode_base + blockIdx.z;
    const uint16_t *Ah, *Al, *Wh, *Wl;
    const float* bias;
    if (mode == 0)      { Ah = g_aq_hi;  Al = g_aq_lo;  Wh = g_wq_hi; Wl = g_wq_lo; bias = bq_; }
    else if (mode == 1) { Ah = g_ak_hi;  Al = g_ak_lo;  Wh = g_wk_hi; Wl = g_wk_lo; bias = bk_; }
    else if (mode == 2) { Ah = g_av_hi;  Al = g_av_lo;  Wh = g_wv_hi; Wl = g_wv_lo; bias = bv_; }
    else                { Ah = g_ctx_hi; Al = g_ctx_lo; Wh = g_wo_hi; Wl = g_wo_lo; bias = bo_; }

    const int tid  = threadIdx.x;
    const int lane = tid & 31, w = tid >> 5;
    const int wm = w & 1, wn = w >> 1;
    const int g  = lane >> 2, tq = lane & 3;
    const int m0 = blockIdx.y * BM, n0 = blockIdx.x * BN;

    const int lq  = lane & 7, cls = lane >> 3;
    const uint32_t a_hi_off = (uint32_t)((((cls & 1) * 8 + lq) * BKP + (cls >> 1) * 8) * 2);
    const uint32_t a_lo_off = a_hi_off + OFF_ALO * 2;
    const uint32_t w_off = (uint32_t)(((wn * 32 + lq) * BKP + (cls & 1) * 8) * 2)
                         + (uint32_t)((cls < 2 ? OFF_WHI : OFF_WLO) * 2);

    const int st_row0 = tid >> 2;
    const int st_c0   = (tid & 3) << 3;
    const int st_row1 = (tid + 256) >> 2;
    const int st_c1   = ((tid + 256) & 3) << 3;
    const uint32_t so0 = (uint32_t)((st_row0 * BKP + st_c0) * 2);
    const uint32_t so1 = (uint32_t)((st_row1 * BKP + st_c1) * 2);

    float acc[4][4][4];
#pragma unroll
    for (int mi = 0; mi < 4; mi++)
#pragma unroll
        for (int ni = 0; ni < 4; ni++)
#pragma unroll
            for (int r = 0; r < 4; r++) acc[mi][ni][r] = 0.f;

    auto prefetch = [&](int kt, int st) {
        uint32_t sb = smbase + (uint32_t)st * ST_BYTES;
        size_t a0 = (size_t)(m0 + st_row0) * D_MODEL + kt + st_c0;
        size_t w0s = (size_t)(n0 + st_row0) * D_MODEL + kt + st_c0;
        CP_ASYNC16(sb + so0,                &Ah[a0]);
        CP_ASYNC16(sb + so0 + OFF_ALO * 2,  &Al[a0]);
        CP_ASYNC16(sb + so0 + OFF_WHI * 2,  &Wh[w0s]);
        CP_ASYNC16(sb + so0 + OFF_WLO * 2,  &Wl[w0s]);
        size_t a1 = (size_t)(m0 + st_row1) * D_MODEL + kt + st_c1;
        size_t w1s = (size_t)(n0 + st_row1) * D_MODEL + kt + st_c1;
        CP_ASYNC16(sb + so1,                &Ah[a1]);
        CP_ASYNC16(sb + so1 + OFF_ALO * 2,  &Al[a1]);
        CP_ASYNC16(sb + so1 + OFF_WHI * 2,  &Wh[w1s]);
        CP_ASYNC16(sb + so1 + OFF_WLO * 2,  &Wl[w1s]);
    };

    const int NT = D_MODEL / BK;   // 32
    prefetch(0, 0);
    CP_COMMIT();

    for (int t = 0; t < NT; t++) {
        if (t + 1 < NT) {
            prefetch((t + 1) * BK, (t + 1) & 1);
            CP_COMMIT();
            CP_WAIT1();
        } else {
            CP_WAIT0();
        }
        __syncthreads();

        const uint32_t sb = smbase + (uint32_t)(t & 1) * ST_BYTES;
#pragma unroll
        for (int s = 0; s < 2; s++) {
            uint32_t bhf[4][2], blf[4][2];
#pragma unroll
            for (int ni = 0; ni < 4; ni++) {
                uint32_t addr = sb + w_off + (uint32_t)((ni * 8 * BKP + s * 16) * 2);
                ldmx4(bhf[ni][0], bhf[ni][1], blf[ni][0], blf[ni][1], addr);
            }
#pragma unroll
            for (int mi = 0; mi < 4; mi++) {
                uint32_t moff = (uint32_t)(((wm * 64 + mi * 16) * BKP + s * 16) * 2);
                uint32_t ah[4], al[4];
                ldmx4(ah[0], ah[1], ah[2], ah[3], sb + a_hi_off + moff);
                ldmx4(al[0], al[1], al[2], al[3], sb + a_lo_off + moff);
#pragma unroll
                for (int ni = 0; ni < 4; ni++) {
                    mma16816(acc[mi][ni], ah, bhf[ni]);
                    mma16816(acc[mi][ni], ah, blf[ni]);
                    mma16816(acc[mi][ni], al, bhf[ni]);
                }
            }
        }
        __syncthreads();
    }

    const float sc = (mode == 0) ? 0.125f : 1.0f;

#pragma unroll
    for (int mi = 0; mi < 4; mi++) {
#pragma unroll
        for (int ni = 0; ni < 4; ni++) {
#pragma unroll
            for (int half = 0; half < 2; half++) {
                int m = m0 + wm * 64 + mi * 16 + g + half * 8;
                int nb = n0 + wn * 32 + ni * 8 + tq * 2;
                float v0 = acc[mi][ni][half * 2 + 0] + bias[nb];
                float v1 = acc[mi][ni][half * 2 + 1] + bias[nb + 1];
                if (mode == 3) {
                    Cflat[(size_t)m * D_MODEL + nb]     = v0;
                    Cflat[(size_t)m * D_MODEL + nb + 1] = v1;
                } else {
                    int b_ = m >> 11, ss = m & (SEQ - 1);
                    int h  = nb >> 6, d  = nb & 63;
                    int bh = b_ * HEADS + h;
                    if (mode == 2) {
                        uint16_t vh, vl;
                        size_t idx = ((size_t)bh * DK + d) * SEQ + ss;
                        split_bf16(v0, vh, vl);
                        g_vt_hi[idx] = vh; g_vt_lo[idx] = vl;
                        split_bf16(v1, vh, vl);
                        g_vt_hi[idx + SEQ] = vh; g_vt_lo[idx + SEQ] = vl;
                    } else {
                        uint32_t ph, pl;
                        split_pack2(v0 * sc, v1 * sc, ph, pl);
                        size_t idx = ((size_t)bh * SEQ + ss) * DK + d;
                        if (mode == 0) {
                            *(uint32_t*)&g_q_hi[idx] = ph;
                            *(uint32_t*)&g_q_lo[idx] = pl;
                        } else {
                            *(uint32_t*)&g_k_hi[idx] = ph;
                            *(uint32_t*)&g_k_lo[idx] = pl;
                        }
                    }
                }
            }
        }
    }
}

// ---------------- flash attention v3: double-buffered 32-key tiles ----------
// 128 threads = 4 warps; warp w owns q rows [w*16, w*16+16) of a 64-row block.
// 2-stage cp.async ring; staging of tile t+1 overlaps compute of tile t.
#define KTILE 32
#define KSTR  72    // K row stride (elems); 144B rows -> conflict-free ldmatrix
#define VSTR  40    // V^T row stride (elems); 80B rows, 16B-aligned, conflict-free
// stage layout (BYTES): Khi@0 (32*144=4608) Klo@4608 Vhi@9216 (64*80=5120) Vlo@14336
#define FST_BYTES 19456
#define F_KLO 4608
#define F_VHI 9216
#define F_VLO 14336

__global__ __launch_bounds__(128, 4) void flash_mma_k()
{
    extern __shared__ uint16_t smu[];
    const uint32_t smbase = smem_u32(smu);
    // Q staged transiently in stage0 region: Qhi[64][KSTR] @0, Qlo @9216B
    uint16_t* Qhi = smu;
    uint16_t* Qlo = smu + 4608;   // elems (9216 B)

    const int tid  = threadIdx.x;
    const int lane = tid & 31, w = tid >> 5;
    const int g = lane >> 2, tq = lane & 3;
    const int bh = blockIdx.y;
    const int b  = bh >> 4, h = bh & 15;
    const int qbase = blockIdx.x * 64;
    const int q0 = w * 16;

    const int lq = lane & 7, cls = lane >> 3;
    // per-stage ldmatrix offsets (add sb per tile)
    const uint32_t k_off = (uint32_t)(cls < 2 ? 0 : F_KLO)
                         + (uint32_t)(lq * (KSTR * 2) + (cls & 1) * 16);
    const uint32_t v_off = (uint32_t)(cls < 2 ? F_VHI : F_VLO)
                         + (uint32_t)(lq * (VSTR * 2) + (cls & 1) * 16);

    // ---- stage Q (cp.async into stage0 region), extract fragments ----
#pragma unroll
    for (int l = 0; l < 4; l++) {
        int id  = tid + l * 128;
        int row = id >> 3;
        int dc  = (id & 7) << 3;
        size_t src = ((size_t)bh * SEQ + qbase + row) * DK + dc;
        CP_ASYNC16(smem_u32(&Qhi[row * KSTR + dc]), &g_q_hi[src]);
        CP_ASYNC16(smem_u32(&Qlo[row * KSTR + dc]), &g_q_lo[src]);
    }
    CP_COMMIT();
    CP_WAIT0();
    __syncthreads();

    uint32_t aqh[4][4], aql[4][4];
#pragma unroll
    for (int t = 0; t < 4; t++) {
        int c0 = 16 * t + 2 * tq;
        aqh[t][0] = *(const uint32_t*)&Qhi[(q0 + g    ) * KSTR + c0];
        aqh[t][1] = *(const uint32_t*)&Qhi[(q0 + g + 8) * KSTR + c0];
        aqh[t][2] = *(const uint32_t*)&Qhi[(q0 + g    ) * KSTR + c0 + 8];
        aqh[t][3] = *(const uint32_t*)&Qhi[(q0 + g + 8) * KSTR + c0 + 8];
        aql[t][0] = *(const uint32_t*)&Qlo[(q0 + g    ) * KSTR + c0];
        aql[t][1] = *(const uint32_t*)&Qlo[(q0 + g + 8) * KSTR + c0];
        aql[t][2] = *(const uint32_t*)&Qlo[(q0 + g    ) * KSTR + c0 + 8];
        aql[t][3] = *(const uint32_t*)&Qlo[(q0 + g + 8) * KSTR + c0 + 8];
    }
    __syncthreads();   // all warps done reading Q smem before stage0 reuse

    // staging lambda: one 32-key tile into stage st
    auto fetch = [&](int kt, int st) {
        uint32_t sb = smbase + (uint32_t)st * FST_BYTES;
#pragma unroll
        for (int l = 0; l < 2; l++) {
            int id  = tid + l * 128;
            int row = id >> 3;                 // 0..31
            int c   = (id & 7) << 3;           // 0..56
            size_t ksrc = ((size_t)bh * SEQ + kt + row) * DK + c;
            CP_ASYNC16(sb + (uint32_t)(row * (KSTR * 2) + c * 2),         &g_k_hi[ksrc]);
            CP_ASYNC16(sb + F_KLO + (uint32_t)(row * (KSTR * 2) + c * 2), &g_k_lo[ksrc]);
        }
#pragma unroll
        for (int l = 0; l < 2; l++) {
            int id  = tid + l * 128;
            int row = id >> 2;                 // 0..63 (d)
            int c   = (id & 3) << 3;           // 0..24 (key)
            size_t vsrc = ((size_t)bh * DK + row) * SEQ + kt + c;
            CP_ASYNC16(sb + F_VHI + (uint32_t)(row * (VSTR * 2) + c * 2), &g_vt_hi[vsrc]);
            CP_ASYNC16(sb + F_VLO + (uint32_t)(row * (VSTR * 2) + c * 2), &g_vt_lo[vsrc]);
        }
    };

    float m0 = -1e30f, m1 = -1e30f, l0 = 0.f, l1 = 0.f;
    float oacc[8][4];
#pragma unroll
    for (int dj = 0; dj < 8; dj++)
#pragma unroll
        for (int r = 0; r < 4; r++) oacc[dj][r] = 0.f;

    const int NT = SEQ / KTILE;   // 64
    fetch(0, 0);
    CP_COMMIT();

    for (int t = 0; t < NT; t++) {
        if (t + 1 < NT) {
            fetch((t + 1) * KTILE, (t + 1) & 1);
            CP_COMMIT();
            CP_WAIT1();
        } else {
            CP_WAIT0();
        }
        __syncthreads();

        const uint32_t sb = smbase + (uint32_t)(t & 1) * FST_BYTES;

        // ---- S = Q.K^T (3-pass split) : 4 key-blocks x 4 k16 steps ----
        float sacc[4][4];
#pragma unroll
        for (int j = 0; j < 4; j++)
#pragma unroll
            for (int r = 0; r < 4; r++) sacc[j][r] = 0.f;

#pragma unroll
        for (int j = 0; j < 4; j++) {
            uint32_t ja = sb + k_off + (uint32_t)(8 * j * (KSTR * 2));
#pragma unroll
            for (int tt = 0; tt < 4; tt++) {
                uint32_t bhf[2], blf[2];
                ldmx4(bhf[0], bhf[1], blf[0], blf[1], ja + (uint32_t)(tt * 32));
                mma16816(sacc[j], aqh[tt], bhf);
                mma16816(sacc[j], aqh[tt], blf);
                mma16816(sacc[j], aql[tt], bhf);
            }
        }

        // ---- online softmax (16 scores per lane-row-pair) ----
        float mx0 = -1e30f, mx1 = -1e30f;
#pragma unroll
        for (int j = 0; j < 4; j++) {
            mx0 = fmaxf(mx0, fmaxf(sacc[j][0], sacc[j][1]));
            mx1 = fmaxf(mx1, fmaxf(sacc[j][2], sacc[j][3]));
        }
#pragma unroll
        for (int off = 1; off <= 2; off <<= 1) {
            mx0 = fmaxf(mx0, __shfl_xor_sync(0xffffffffu, mx0, off));
            mx1 = fmaxf(mx1, __shfl_xor_sync(0xffffffffu, mx1, off));
        }
        float mn0 = fmaxf(m0, mx0), mn1 = fmaxf(m1, mx1);
        float al0 = __expf(m0 - mn0), al1 = __expf(m1 - mn1);
        m0 = mn0; m1 = mn1;

        float rs0 = 0.f, rs1 = 0.f;
#pragma unroll
        for (int j = 0; j < 4; j++) {
            sacc[j][0] = __expf(sacc[j][0] - mn0);
            sacc[j][1] = __expf(sacc[j][1] - mn0);
            sacc[j][2] = __expf(sacc[j][2] - mn1);
            sacc[j][3] = __expf(sacc[j][3] - mn1);
            rs0 += sacc[j][0] + sacc[j][1];
            rs1 += sacc[j][2] + sacc[j][3];
        }
#pragma unroll
        for (int off = 1; off <= 2; off <<= 1) {
            rs0 += __shfl_xor_sync(0xffffffffu, rs0, off);
            rs1 += __shfl_xor_sync(0xffffffffu, rs1, off);
        }
        l0 = l0 * al0 + rs0;
        l1 = l1 * al1 + rs1;
#pragma unroll
        for (int dj = 0; dj < 8; dj++) {
            oacc[dj][0] *= al0; oacc[dj][1] *= al0;
            oacc[dj][2] *= al1; oacc[dj][3] *= al1;
        }

        // ---- P -> split bf16 A-fragments (2 k16 steps) ----
        uint32_t pah[2][4], pal[2][4];
#pragma unroll
        for (int tt = 0; tt < 2; tt++) {
            split_pack2(sacc[2*tt    ][0], sacc[2*tt    ][1], pah[tt][0], pal[tt][0]);
            split_pack2(sacc[2*tt    ][2], sacc[2*tt    ][3], pah[tt][1], pal[tt][1]);
            split_pack2(sacc[2*tt + 1][0], sacc[2*tt + 1][1], pah[tt][2], pal[tt][2]);
            split_pack2(sacc[2*tt + 1][2], sacc[2*tt + 1][3], pah[tt][3], pal[tt][3]);
        }

        // ---- O += P.V (3-pass split) : 8 d-blocks x 2 k16 steps ----
#pragma unroll
        for (int dj = 0; dj < 8; dj++) {
            uint32_t ja = sb + v_off + (uint32_t)(8 * dj * (VSTR * 2));
#pragma unroll
            for (int tt = 0; tt < 2; tt++) {
                uint32_t bhf[2], blf[2];
                ldmx4(bhf[0], bhf[1], blf[0], blf[1], ja + (uint32_t)(tt * 32));
                mma16816(oacc[dj], pah[tt], bhf);
                mma16816(oacc[dj], pah[tt], blf);
                mma16816(oacc[dj], pal[tt], bhf);
            }
        }
        __syncthreads();
    }

    // epilogue: normalize, split, write ctx (split bf16, concat layout)
    float inv0 = 1.f / l0, inv1 = 1.f / l1;
    int s0 = qbase + q0 + g;
    int s1 = s0 + 8;
#pragma unroll
    for (int dj = 0; dj < 8; dj++) {
        int d = h * DK + 8 * dj + 2 * tq;
        uint32_t h0, lo0, h1, lo1;
        split_pack2(oacc[dj][0] * inv0, oacc[dj][1] * inv0, h0, lo0);
        split_pack2(oacc[dj][2] * inv1, oacc[dj][3] * inv1, h1, lo1);
        size_t i0 = (size_t)(b * SEQ + s0) * D_MODEL + d;
        size_t i1 = (size_t)(b * SEQ + s1) * D_MODEL + d;
        *(uint32_t*)&g_ctx_hi[i0] = h0;
        *(uint32_t*)&g_ctx_lo[i0] = lo0;
        *(uint32_t*)&g_ctx_hi[i1] = h1;
        *(uint32_t*)&g_ctx_lo[i1] = lo1;
    }
}

// ---------------- launch ----------------------------------------------------
extern "C" void kernel_launch(void* const* d_in, const int* in_sizes, int n_in,
                              void* d_out, int out_size)
{
    const float* q  = (const float*)d_in[0];
    const float* k  = (const float*)d_in[1];
    const float* v  = (const float*)d_in[2];
    const float* wq = (const float*)d_in[3];
    const float* bq = (const float*)d_in[4];
    const float* wk = (const float*)d_in[5];
    const float* bk = (const float*)d_in[6];
    const float* wv = (const float*)d_in[7];
    const float* bv = (const float*)d_in[8];
    const float* wo = (const float*)d_in[9];
    const float* bo = (const float*)d_in[10];
    float* out = (float*)d_out;

    const int WELEM = D_MODEL * D_MODEL;   // 1M
    const int AELEM = M_TOK * D_MODEL;     // 4M

    split_w_k<<<dim3(WELEM / 1024, 4), 256>>>(wq, wk, wv, wo);
    split_a_k<<<dim3(AELEM / 1024, 3), 256>>>(q, k, v);

    const int gemm_smem = 2 * ST_BYTES;    // 81920
    cudaFuncSetAttribute(mma_gemm3_k,
                         cudaFuncAttributeMaxDynamicSharedMemorySize, gemm_smem);

    // fused Q/K/V projections: grid.z selects mode
    mma_gemm3_k<<<dim3(D_MODEL / BN, M_TOK / BM, 3), 256, gemm_smem>>>(
        bq, bk, bv, bo, nullptr, 0);

    const int fa_smem = 2 * FST_BYTES;     // 38912
    cudaFuncSetAttribute(flash_mma_k,
                         cudaFuncAttributeMaxDynamicSharedMemorySize, fa_smem);
    flash_mma_k<<<dim3(SEQ / 64, BH), 128, fa_smem>>>();

    // output projection
    mma_gemm3_k<<<dim3(D_MODEL / BN, M_TOK / BM, 1), 256, gemm_smem>>>(
        bq, bk, bv, bo, out, 3);
}

// round 17
// speedup vs baseline: 1.3569x; 1.0218x over previous
#include <cuda_runtime.h>
#include <cuda_bf16.h>
#include <stdint.h>

#define D_MODEL 1024
#define HEADS   16
#define DK      64
#define BATCH   2
#define SEQ     2048
#define M_TOK   (BATCH * SEQ)
#define BH      (BATCH * HEADS)

// ---------------- scratch (static device globals; no runtime alloc) ----------
__device__ uint16_t g_wq_hi[D_MODEL * D_MODEL], g_wq_lo[D_MODEL * D_MODEL];
__device__ uint16_t g_wk_hi[D_MODEL * D_MODEL], g_wk_lo[D_MODEL * D_MODEL];
__device__ uint16_t g_wv_hi[D_MODEL * D_MODEL], g_wv_lo[D_MODEL * D_MODEL];
__device__ uint16_t g_wo_hi[D_MODEL * D_MODEL], g_wo_lo[D_MODEL * D_MODEL];
__device__ uint16_t g_aq_hi[M_TOK * D_MODEL], g_aq_lo[M_TOK * D_MODEL];
__device__ uint16_t g_ak_hi[M_TOK * D_MODEL], g_ak_lo[M_TOK * D_MODEL];
__device__ uint16_t g_av_hi[M_TOK * D_MODEL], g_av_lo[M_TOK * D_MODEL];
// projected: Q,K [bh][s][d] (Q pre-scaled by 0.125*log2e); V^T [bh][d][s]
__device__ uint16_t g_q_hi[BH * SEQ * DK], g_q_lo[BH * SEQ * DK];
__device__ uint16_t g_k_hi[BH * SEQ * DK], g_k_lo[BH * SEQ * DK];
__device__ uint16_t g_vt_hi[BH * DK * SEQ], g_vt_lo[BH * DK * SEQ];
// attention output, split [B,S,D_MODEL]
__device__ uint16_t g_ctx_hi[M_TOK * D_MODEL], g_ctx_lo[M_TOK * D_MODEL];

// ---------------- helpers ----------------------------------------------------
__device__ __forceinline__ uint16_t f2bf_bits(float x) {
    __nv_bfloat16 h = __float2bfloat16(x);
    return *reinterpret_cast<uint16_t*>(&h);
}
__device__ __forceinline__ float bfbits2f(uint16_t b) {
    __nv_bfloat16 h = *reinterpret_cast<__nv_bfloat16*>(&b);
    return __bfloat162float(h);
}
__device__ __forceinline__ void split_bf16(float x, uint16_t& hi, uint16_t& lo) {
    hi = f2bf_bits(x);
    lo = f2bf_bits(x - bfbits2f(hi));
}
// fast 2-float split+pack: low 16 bits = first element (rn rounding, same as before)
__device__ __forceinline__ void split_pack2(float p0, float p1,
                                            uint32_t& hi, uint32_t& lo) {
    uint32_t h;
    asm("cvt.rn.bf16x2.f32 %0, %1, %2;" : "=r"(h) : "f"(p1), "f"(p0));
    float h0 = __uint_as_float(h << 16);
    float h1 = __uint_as_float(h & 0xFFFF0000u);
    float l0 = p0 - h0;
    float l1 = p1 - h1;
    uint32_t l;
    asm("cvt.rn.bf16x2.f32 %0, %1, %2;" : "=r"(l) : "f"(l1), "f"(l0));
    hi = h; lo = l;
}

__device__ __forceinline__ void mma16816(float* c, const uint32_t* a, const uint32_t* b) {
    asm volatile(
        "mma.sync.aligned.m16n8k16.row.col.f32.bf16.bf16.f32 "
        "{%0,%1,%2,%3}, {%4,%5,%6,%7}, {%8,%9}, {%0,%1,%2,%3};"
        : "+f"(c[0]), "+f"(c[1]), "+f"(c[2]), "+f"(c[3])
        : "r"(a[0]), "r"(a[1]), "r"(a[2]), "r"(a[3]), "r"(b[0]), "r"(b[1]));
}
__device__ __forceinline__ void ldmx4(uint32_t& r0, uint32_t& r1,
                                      uint32_t& r2, uint32_t& r3, uint32_t addr) {
    asm volatile("ldmatrix.sync.aligned.m8n8.x4.shared.b16 {%0,%1,%2,%3}, [%4];"
        : "=r"(r0), "=r"(r1), "=r"(r2), "=r"(r3) : "r"(addr));
}
__device__ __forceinline__ uint32_t smem_u32(const void* p) {
    return (uint32_t)__cvta_generic_to_shared(p);
}
#define CP_ASYNC16(dst, src) \
    asm volatile("cp.async.cg.shared.global [%0], [%1], 16;" :: "r"(dst), "l"(src))
#define CP_COMMIT() asm volatile("cp.async.commit_group;")
#define CP_WAIT0()  asm volatile("cp.async.wait_group 0;")
#define CP_WAIT1()  asm volatile("cp.async.wait_group 1;")

#define LOG2E 1.4426950408889634f

// ---------------- batched fp32 -> split bf16 (MLP=4) ------------------------
__global__ __launch_bounds__(256) void split_w_k(
    const float* __restrict__ w0, const float* __restrict__ w1,
    const float* __restrict__ w2, const float* __restrict__ w3)
{
    const float* src;
    uint16_t *hi, *lo;
    switch (blockIdx.y) {
        case 0: src = w0; hi = g_wq_hi; lo = g_wq_lo; break;
        case 1: src = w1; hi = g_wk_hi; lo = g_wk_lo; break;
        case 2: src = w2; hi = g_wv_hi; lo = g_wv_lo; break;
        default: src = w3; hi = g_wo_hi; lo = g_wo_lo; break;
    }
    int base4 = blockIdx.x * 1024 + threadIdx.x;   // float4 index
    float4 v[4];
#pragma unroll
    for (int j = 0; j < 4; j++) v[j] = *(const float4*)&src[(base4 + j * 256) * 4];
#pragma unroll
    for (int j = 0; j < 4; j++) {
        int i = (base4 + j * 256) * 4;
        uint32_t h0, l0, h1, l1;
        split_pack2(v[j].x, v[j].y, h0, l0);
        split_pack2(v[j].z, v[j].w, h1, l1);
        *(uint32_t*)&hi[i]     = h0;
        *(uint32_t*)&hi[i + 2] = h1;
        *(uint32_t*)&lo[i]     = l0;
        *(uint32_t*)&lo[i + 2] = l1;
    }
}
__global__ __launch_bounds__(256) void split_a_k(
    const float* __restrict__ a0, const float* __restrict__ a1,
    const float* __restrict__ a2)
{
    const float* src;
    uint16_t *hi, *lo;
    switch (blockIdx.y) {
        case 0: src = a0; hi = g_aq_hi; lo = g_aq_lo; break;
        case 1: src = a1; hi = g_ak_hi; lo = g_ak_lo; break;
        default: src = a2; hi = g_av_hi; lo = g_av_lo; break;
    }
    int base4 = blockIdx.x * 1024 + threadIdx.x;
    float4 v[4];
#pragma unroll
    for (int j = 0; j < 4; j++) v[j] = *(const float4*)&src[(base4 + j * 256) * 4];
#pragma unroll
    for (int j = 0; j < 4; j++) {
        int i = (base4 + j * 256) * 4;
        uint32_t h0, l0, h1, l1;
        split_pack2(v[j].x, v[j].y, h0, l0);
        split_pack2(v[j].z, v[j].w, h1, l1);
        *(uint32_t*)&hi[i]     = h0;
        *(uint32_t*)&hi[i + 2] = h1;
        *(uint32_t*)&lo[i]     = l0;
        *(uint32_t*)&lo[i + 2] = l1;
    }
}

// ---------------- split-bf16 tensor GEMM v4: 64x64 warp tiles ---------------
// C = A[M,K] * W[N,K]^T + bias;  C ~= Ah*Wh + Ah*Wl + Al*Wh.
// 128 threads = 4 warps as 2(M) x 2(N); warp tile 64x64. cp.async 2-stage.
// mode = mode_base + blockIdx.z: 0->g_q(*0.125*log2e), 1->g_k,
// 2->g_vt (transposed), 3->Cflat fp32.
#define BM  128
#define BN  128
#define BK  32
#define BKP 40
#define ST_BYTES 40960
#define OFF_ALO  5120
#define OFF_WHI  10240
#define OFF_WLO  15360

__global__ __launch_bounds__(128, 2) void mma_gemm4_k(
    const float* __restrict__ bq_, const float* __restrict__ bk_,
    const float* __restrict__ bv_, const float* __restrict__ bo_,
    float* __restrict__ Cflat, int mode_base)
{
    extern __shared__ uint16_t gsm[];
    const uint32_t smbase = smem_u32(gsm);

    const int mode = mode_base + blockIdx.z;
    const uint16_t *Ah, *Al, *Wh, *Wl;
    const float* bias;
    if (mode == 0)      { Ah = g_aq_hi;  Al = g_aq_lo;  Wh = g_wq_hi; Wl = g_wq_lo; bias = bq_; }
    else if (mode == 1) { Ah = g_ak_hi;  Al = g_ak_lo;  Wh = g_wk_hi; Wl = g_wk_lo; bias = bk_; }
    else if (mode == 2) { Ah = g_av_hi;  Al = g_av_lo;  Wh = g_wv_hi; Wl = g_wv_lo; bias = bv_; }
    else                { Ah = g_ctx_hi; Al = g_ctx_lo; Wh = g_wo_hi; Wl = g_wo_lo; bias = bo_; }

    const int tid  = threadIdx.x;
    const int lane = tid & 31, w = tid >> 5;
    const int wm = w & 1, wn = w >> 1;          // 2 x 2 warp grid
    const int g  = lane >> 2, tq = lane & 3;
    const int m0 = blockIdx.y * BM, n0 = blockIdx.x * BN;

    const int lq  = lane & 7, cls = lane >> 3;
    const uint32_t a_hi_off = (uint32_t)((((cls & 1) * 8 + lq) * BKP + (cls >> 1) * 8) * 2);
    const uint32_t a_lo_off = a_hi_off + OFF_ALO * 2;
    const uint32_t w_off = (uint32_t)(((wn * 64 + lq) * BKP + (cls & 1) * 8) * 2)
                         + (uint32_t)((cls < 2 ? OFF_WHI : OFF_WLO) * 2);

    // staging: 512 (row,chunk) ids over 128 threads -> 4 per thread, 4 arrays
    int st_row[4], st_c[4];
    uint32_t so[4];
#pragma unroll
    for (int l = 0; l < 4; l++) {
        int id = tid + l * 128;
        st_row[l] = id >> 2;
        st_c[l]   = (id & 3) << 3;
        so[l]     = (uint32_t)((st_row[l] * BKP + st_c[l]) * 2);
    }

    float acc[4][8][4];
#pragma unroll
    for (int mi = 0; mi < 4; mi++)
#pragma unroll
        for (int ni = 0; ni < 8; ni++)
#pragma unroll
            for (int r = 0; r < 4; r++) acc[mi][ni][r] = 0.f;

    auto prefetch = [&](int kt, int st) {
        uint32_t sb = smbase + (uint32_t)st * ST_BYTES;
#pragma unroll
        for (int l = 0; l < 4; l++) {
            size_t ga = (size_t)(m0 + st_row[l]) * D_MODEL + kt + st_c[l];
            size_t gw = (size_t)(n0 + st_row[l]) * D_MODEL + kt + st_c[l];
            CP_ASYNC16(sb + so[l],                &Ah[ga]);
            CP_ASYNC16(sb + so[l] + OFF_ALO * 2,  &Al[ga]);
            CP_ASYNC16(sb + so[l] + OFF_WHI * 2,  &Wh[gw]);
            CP_ASYNC16(sb + so[l] + OFF_WLO * 2,  &Wl[gw]);
        }
    };

    const int NT = D_MODEL / BK;   // 32
    prefetch(0, 0);
    CP_COMMIT();

    for (int t = 0; t < NT; t++) {
        if (t + 1 < NT) {
            prefetch((t + 1) * BK, (t + 1) & 1);
            CP_COMMIT();
            CP_WAIT1();
        } else {
            CP_WAIT0();
        }
        __syncthreads();

        const uint32_t sb = smbase + (uint32_t)(t & 1) * ST_BYTES;
#pragma unroll
        for (int s = 0; s < 2; s++) {
            uint32_t bhf[8][2], blf[8][2];
#pragma unroll
            for (int ni = 0; ni < 8; ni++) {
                uint32_t addr = sb + w_off + (uint32_t)((ni * 8 * BKP + s * 16) * 2);
                ldmx4(bhf[ni][0], bhf[ni][1], blf[ni][0], blf[ni][1], addr);
            }
#pragma unroll
            for (int mi = 0; mi < 4; mi++) {
                uint32_t moff = (uint32_t)(((wm * 64 + mi * 16) * BKP + s * 16) * 2);
                uint32_t ah[4], al[4];
                ldmx4(ah[0], ah[1], ah[2], ah[3], sb + a_hi_off + moff);
                ldmx4(al[0], al[1], al[2], al[3], sb + a_lo_off + moff);
#pragma unroll
                for (int ni = 0; ni < 8; ni++) {
                    mma16816(acc[mi][ni], ah, bhf[ni]);
                    mma16816(acc[mi][ni], ah, blf[ni]);
                    mma16816(acc[mi][ni], al, bhf[ni]);
                }
            }
        }
        __syncthreads();
    }

    const float sc = (mode == 0) ? (0.125f * LOG2E) : 1.0f;

#pragma unroll
    for (int mi = 0; mi < 4; mi++) {
#pragma unroll
        for (int ni = 0; ni < 8; ni++) {
#pragma unroll
            for (int half = 0; half < 2; half++) {
                int m = m0 + wm * 64 + mi * 16 + g + half * 8;
                int nb = n0 + wn * 64 + ni * 8 + tq * 2;
                float v0 = acc[mi][ni][half * 2 + 0] + bias[nb];
                float v1 = acc[mi][ni][half * 2 + 1] + bias[nb + 1];
                if (mode == 3) {
                    Cflat[(size_t)m * D_MODEL + nb]     = v0;
                    Cflat[(size_t)m * D_MODEL + nb + 1] = v1;
                } else {
                    int b_ = m >> 11, ss = m & (SEQ - 1);
                    int h  = nb >> 6, d  = nb & 63;
                    int bh = b_ * HEADS + h;
                    if (mode == 2) {
                        uint16_t vh, vl;
                        size_t idx = ((size_t)bh * DK + d) * SEQ + ss;
                        split_bf16(v0, vh, vl);
                        g_vt_hi[idx] = vh; g_vt_lo[idx] = vl;
                        split_bf16(v1, vh, vl);
                        g_vt_hi[idx + SEQ] = vh; g_vt_lo[idx + SEQ] = vl;
                    } else {
                        uint32_t ph, pl;
                        split_pack2(v0 * sc, v1 * sc, ph, pl);
                        size_t idx = ((size_t)bh * SEQ + ss) * DK + d;
                        if (mode == 0) {
                            *(uint32_t*)&g_q_hi[idx] = ph;
                            *(uint32_t*)&g_q_lo[idx] = pl;
                        } else {
                            *(uint32_t*)&g_k_hi[idx] = ph;
                            *(uint32_t*)&g_k_lo[idx] = pl;
                        }
                    }
                }
            }
        }
    }
}

// ---------------- flash attention v3: double-buffered 32-key tiles ----------
// 128 threads = 4 warps; warp w owns q rows [w*16, w*16+16) of a 64-row block.
// exp2-domain softmax (Q pre-scaled by 0.125*log2e).
#define KTILE 32
#define KSTR  72
#define VSTR  40
#define FST_BYTES 19456
#define F_KLO 4608
#define F_VHI 9216
#define F_VLO 14336

__global__ __launch_bounds__(128, 4) void flash_mma_k()
{
    extern __shared__ uint16_t smu[];
    const uint32_t smbase = smem_u32(smu);
    uint16_t* Qhi = smu;
    uint16_t* Qlo = smu + 4608;

    const int tid  = threadIdx.x;
    const int lane = tid & 31, w = tid >> 5;
    const int g = lane >> 2, tq = lane & 3;
    const int bh = blockIdx.y;
    const int b  = bh >> 4, h = bh & 15;
    const int qbase = blockIdx.x * 64;
    const int q0 = w * 16;

    const int lq = lane & 7, cls = lane >> 3;
    const uint32_t k_off = (uint32_t)(cls < 2 ? 0 : F_KLO)
                         + (uint32_t)(lq * (KSTR * 2) + (cls & 1) * 16);
    const uint32_t v_off = (uint32_t)(cls < 2 ? F_VHI : F_VLO)
                         + (uint32_t)(lq * (VSTR * 2) + (cls & 1) * 16);

#pragma unroll
    for (int l = 0; l < 4; l++) {
        int id  = tid + l * 128;
        int row = id >> 3;
        int dc  = (id & 7) << 3;
        size_t src = ((size_t)bh * SEQ + qbase + row) * DK + dc;
        CP_ASYNC16(smem_u32(&Qhi[row * KSTR + dc]), &g_q_hi[src]);
        CP_ASYNC16(smem_u32(&Qlo[row * KSTR + dc]), &g_q_lo[src]);
    }
    CP_COMMIT();
    CP_WAIT0();
    __syncthreads();

    uint32_t aqh[4][4], aql[4][4];
#pragma unroll
    for (int t = 0; t < 4; t++) {
        int c0 = 16 * t + 2 * tq;
        aqh[t][0] = *(const uint32_t*)&Qhi[(q0 + g    ) * KSTR + c0];
        aqh[t][1] = *(const uint32_t*)&Qhi[(q0 + g + 8) * KSTR + c0];
        aqh[t][2] = *(const uint32_t*)&Qhi[(q0 + g    ) * KSTR + c0 + 8];
        aqh[t][3] = *(const uint32_t*)&Qhi[(q0 + g + 8) * KSTR + c0 + 8];
        aql[t][0] = *(const uint32_t*)&Qlo[(q0 + g    ) * KSTR + c0];
        aql[t][1] = *(const uint32_t*)&Qlo[(q0 + g + 8) * KSTR + c0];
        aql[t][2] = *(const uint32_t*)&Qlo[(q0 + g    ) * KSTR + c0 + 8];
        aql[t][3] = *(const uint32_t*)&Qlo[(q0 + g + 8) * KSTR + c0 + 8];
    }
    __syncthreads();

    auto fetch = [&](int kt, int st) {
        uint32_t sb = smbase + (uint32_t)st * FST_BYTES;
#pragma unroll
        for (int l = 0; l < 2; l++) {
            int id  = tid + l * 128;
            int row = id >> 3;
            int c   = (id & 7) << 3;
            size_t ksrc = ((size_t)bh * SEQ + kt + row) * DK + c;
            CP_ASYNC16(sb + (uint32_t)(row * (KSTR * 2) + c * 2),         &g_k_hi[ksrc]);
            CP_ASYNC16(sb + F_KLO + (uint32_t)(row * (KSTR * 2) + c * 2), &g_k_lo[ksrc]);
        }
#pragma unroll
        for (int l = 0; l < 2; l++) {
            int id  = tid + l * 128;
            int row = id >> 2;
            int c   = (id & 3) << 3;
            size_t vsrc = ((size_t)bh * DK + row) * SEQ + kt + c;
            CP_ASYNC16(sb + F_VHI + (uint32_t)(row * (VSTR * 2) + c * 2), &g_vt_hi[vsrc]);
            CP_ASYNC16(sb + F_VLO + (uint32_t)(row * (VSTR * 2) + c * 2), &g_vt_lo[vsrc]);
        }
    };

    float m0 = -1e30f, m1 = -1e30f, l0 = 0.f, l1 = 0.f;
    float oacc[8][4];
#pragma unroll
    for (int dj = 0; dj < 8; dj++)
#pragma unroll
        for (int r = 0; r < 4; r++) oacc[dj][r] = 0.f;

    const int NT = SEQ / KTILE;
    fetch(0, 0);
    CP_COMMIT();

    for (int t = 0; t < NT; t++) {
        if (t + 1 < NT) {
            fetch((t + 1) * KTILE, (t + 1) & 1);
            CP_COMMIT();
            CP_WAIT1();
        } else {
            CP_WAIT0();
        }
        __syncthreads();

        const uint32_t sb = smbase + (uint32_t)(t & 1) * FST_BYTES;

        float sacc[4][4];
#pragma unroll
        for (int j = 0; j < 4; j++)
#pragma unroll
            for (int r = 0; r < 4; r++) sacc[j][r] = 0.f;

#pragma unroll
        for (int j = 0; j < 4; j++) {
            uint32_t ja = sb + k_off + (uint32_t)(8 * j * (KSTR * 2));
#pragma unroll
            for (int tt = 0; tt < 4; tt++) {
                uint32_t bhf[2], blf[2];
                ldmx4(bhf[0], bhf[1], blf[0], blf[1], ja + (uint32_t)(tt * 32));
                mma16816(sacc[j], aqh[tt], bhf);
                mma16816(sacc[j], aqh[tt], blf);
                mma16816(sacc[j], aql[tt], bhf);
            }
        }

        // ---- online softmax (log2 domain; scores are already *log2e) ----
        float mx0 = -1e30f, mx1 = -1e30f;
#pragma unroll
        for (int j = 0; j < 4; j++) {
            mx0 = fmaxf(mx0, fmaxf(sacc[j][0], sacc[j][1]));
            mx1 = fmaxf(mx1, fmaxf(sacc[j][2], sacc[j][3]));
        }
#pragma unroll
        for (int off = 1; off <= 2; off <<= 1) {
            mx0 = fmaxf(mx0, __shfl_xor_sync(0xffffffffu, mx0, off));
            mx1 = fmaxf(mx1, __shfl_xor_sync(0xffffffffu, mx1, off));
        }
        float mn0 = fmaxf(m0, mx0), mn1 = fmaxf(m1, mx1);
        float al0 = exp2f(m0 - mn0), al1 = exp2f(m1 - mn1);
        m0 = mn0; m1 = mn1;

        float rs0 = 0.f, rs1 = 0.f;
#pragma unroll
        for (int j = 0; j < 4; j++) {
            sacc[j][0] = exp2f(sacc[j][0] - mn0);
            sacc[j][1] = exp2f(sacc[j][1] - mn0);
            sacc[j][2] = exp2f(sacc[j][2] - mn1);
            sacc[j][3] = exp2f(sacc[j][3] - mn1);
            rs0 += sacc[j][0] + sacc[j][1];
            rs1 += sacc[j][2] + sacc[j][3];
        }
#pragma unroll
        for (int off = 1; off <= 2; off <<= 1) {
            rs0 += __shfl_xor_sync(0xffffffffu, rs0, off);
            rs1 += __shfl_xor_sync(0xffffffffu, rs1, off);
        }
        l0 = l0 * al0 + rs0;
        l1 = l1 * al1 + rs1;
#pragma unroll
        for (int dj = 0; dj < 8; dj++) {
            oacc[dj][0] *= al0; oacc[dj][1] *= al0;
            oacc[dj][2] *= al1; oacc[dj][3] *= al1;
        }

        uint32_t pah[2][4], pal[2][4];
#pragma unroll
        for (int tt = 0; tt < 2; tt++) {
            split_pack2(sacc[2*tt    ][0], sacc[2*tt    ][1], pah[tt][0], pal[tt][0]);
            split_pack2(sacc[2*tt    ][2], sacc[2*tt    ][3], pah[tt][1], pal[tt][1]);
            split_pack2(sacc[2*tt + 1][0], sacc[2*tt + 1][1], pah[tt][2], pal[tt][2]);
            split_pack2(sacc[2*tt + 1][2], sacc[2*tt + 1][3], pah[tt][3], pal[tt][3]);
        }

#pragma unroll
        for (int dj = 0; dj < 8; dj++) {
            uint32_t ja = sb + v_off + (uint32_t)(8 * dj * (VSTR * 2));
#pragma unroll
            for (int tt = 0; tt < 2; tt++) {
                uint32_t bhf[2], blf[2];
                ldmx4(bhf[0], bhf[1], blf[0], blf[1], ja + (uint32_t)(tt * 32));
                mma16816(oacc[dj], pah[tt], bhf);
                mma16816(oacc[dj], pah[tt], blf);
                mma16816(oacc[dj], pal[tt], bhf);
            }
        }
        __syncthreads();
    }

    float inv0 = 1.f / l0, inv1 = 1.f / l1;
    int s0 = qbase + q0 + g;
    int s1 = s0 + 8;
#pragma unroll
    for (int dj = 0; dj < 8; dj++) {
        int d = h * DK + 8 * dj + 2 * tq;
        uint32_t h0, lo0, h1, lo1;
        split_pack2(oacc[dj][0] * inv0, oacc[dj][1] * inv0, h0, lo0);
        split_pack2(oacc[dj][2] * inv1, oacc[dj][3] * inv1, h1, lo1);
        size_t i0 = (size_t)(b * SEQ + s0) * D_MODEL + d;
        size_t i1 = (size_t)(b * SEQ + s1) * D_MODEL + d;
        *(uint32_t*)&g_ctx_hi[i0] = h0;
        *(uint32_t*)&g_ctx_lo[i0] = lo0;
        *(uint32_t*)&g_ctx_hi[i1] = h1;
        *(uint32_t*)&g_ctx_lo[i1] = lo1;
    }
}

// ---------------- launch ----------------------------------------------------
extern "C" void kernel_launch(void* const* d_in, const int* in_sizes, int n_in,
                              void* d_out, int out_size)
{
    const float* q  = (const float*)d_in[0];
    const float* k  = (const float*)d_in[1];
    const float* v  = (const float*)d_in[2];
    const float* wq = (const float*)d_in[3];
    const float* bq = (const float*)d_in[4];
    const float* wk = (const float*)d_in[5];
    const float* bk = (const float*)d_in[6];
    const float* wv = (const float*)d_in[7];
    const float* bv = (const float*)d_in[8];
    const float* wo = (const float*)d_in[9];
    const float* bo = (const float*)d_in[10];
    float* out = (float*)d_out;

    // splits: each block handles 1024 float4 (4096 floats)
    split_w_k<<<dim3(D_MODEL * D_MODEL / 4096, 4), 256>>>(wq, wk, wv, wo);
    split_a_k<<<dim3(M_TOK * D_MODEL / 4096, 3), 256>>>(q, k, v);

    const int gemm_smem = 2 * ST_BYTES;    // 81920
    cudaFuncSetAttribute(mma_gemm4_k,
                         cudaFuncAttributeMaxDynamicSharedMemorySize, gemm_smem);

    // fused Q/K/V projections: grid.z selects mode
    mma_gemm4_k<<<dim3(D_MODEL / BN, M_TOK / BM, 3), 128, gemm_smem>>>(
        bq, bk, bv, bo, nullptr, 0);

    const int fa_smem = 2 * FST_BYTES;     // 38912
    cudaFuncSetAttribute(flash_mma_k,
                         cudaFuncAttributeMaxDynamicSharedMemorySize, fa_smem);
    flash_mma_k<<<dim3(SEQ / 64, BH), 128, fa_smem>>>();

    // output projection
    mma_gemm4_k<<<dim3(D_MODEL / BN, M_TOK / BM, 1), 128, gemm_smem>>>(
        bq, bk, bv, bo, out, 3);
}